// round 1
// baseline (speedup 1.0000x reference)
#include <cuda_runtime.h>
#include <cstdint>
#include <cstdio>

#define SEQ   2048
#define BATCH 2
#define MTOK  4096      // BATCH*SEQ tokens
#define HID   4096
#define KPACK 1024      // HID/4 int8s packed per int32
#define NKV   1024      // kv proj width
#define NH    32
#define HD    128

// ---------------- scratch (device globals; no allocation allowed) ----------------
__device__ int   g_xq[MTOK * KPACK];
__device__ float g_inva[MTOK];
__device__ int   g_wqq[HID * KPACK];
__device__ int   g_wkq[NKV * KPACK];
__device__ int   g_wvq[NKV * KPACK];
__device__ int   g_woq[HID * KPACK];
__device__ float g_q[(size_t)MTOK * HID];
__device__ float g_k[(size_t)MTOK * NKV];
__device__ float g_v[(size_t)MTOK * NKV];
__device__ float g_ao[(size_t)MTOK * HID];
__device__ float g_part[4 * 1024];
__device__ float g_wsc[4];

// ---------------- weight scale: mean(|W|), two-pass deterministic ----------------
__global__ void absmean_partial(const float* __restrict__ W, int n, float* __restrict__ part) {
    __shared__ float sb[256];
    int tid = threadIdx.x;
    float s = 0.f;
    for (long i = (long)blockIdx.x * 256 + tid; i < n; i += (long)gridDim.x * 256)
        s += fabsf(W[i]);
    sb[tid] = s; __syncthreads();
    for (int o = 128; o > 0; o >>= 1) {
        if (tid < o) sb[tid] += sb[tid + o];
        __syncthreads();
    }
    if (tid == 0) part[blockIdx.x] = sb[0];
}

__global__ void wscale_final(const float* __restrict__ part, float* __restrict__ wsc) {
    __shared__ float sb[256];
    int i = blockIdx.x, tid = threadIdx.x;
    float s = part[i * 1024 + tid] + part[i * 1024 + tid + 256]
            + part[i * 1024 + tid + 512] + part[i * 1024 + tid + 768];
    sb[tid] = s; __syncthreads();
    for (int o = 128; o > 0; o >>= 1) {
        if (tid < o) sb[tid] += sb[tid + o];
        __syncthreads();
    }
    if (tid == 0) {
        float n = (i == 0 || i == 3) ? 16777216.f : 4194304.f;
        wsc[i] = fmaxf(sb[0] / n, 1e-5f);
    }
}

// ---------------- ternary weight quant: clip(round(W/ws),-1,1) packed int8x4 ----------------
__global__ void quant_w(const float* __restrict__ W, int np, const float* __restrict__ wscp,
                        int* __restrict__ out) {
    int i = blockIdx.x * blockDim.x + threadIdx.x;
    if (i >= np) return;
    float ws = *wscp;
    float4 w = ((const float4*)W)[i];
    int v0 = min(1, max(-1, __float2int_rn(__fdiv_rn(w.x, ws))));
    int v1 = min(1, max(-1, __float2int_rn(__fdiv_rn(w.y, ws))));
    int v2 = min(1, max(-1, __float2int_rn(__fdiv_rn(w.z, ws))));
    int v3 = min(1, max(-1, __float2int_rn(__fdiv_rn(w.w, ws))));
    out[i] = (v0 & 255) | ((v1 & 255) << 8) | ((v2 & 255) << 16) | ((v3 & 255) << 24);
}

// ---------------- per-token int8 activation quant (absmax) ----------------
__global__ void quant_a(const float* __restrict__ X, int* __restrict__ out,
                        float* __restrict__ inva) {
    __shared__ float sb[256];
    int row = blockIdx.x, tid = threadIdx.x;
    const float4* xr = (const float4*)(X + (size_t)row * HID);
    float4 v[4];
    float am = 0.f;
#pragma unroll
    for (int u = 0; u < 4; u++) {
        v[u] = xr[tid + u * 256];
        am = fmaxf(am, fmaxf(fmaxf(fabsf(v[u].x), fabsf(v[u].y)),
                             fmaxf(fabsf(v[u].z), fabsf(v[u].w))));
    }
    sb[tid] = am; __syncthreads();
    for (int o = 128; o > 0; o >>= 1) {
        if (tid < o) sb[tid] = fmaxf(sb[tid], sb[tid + o]);
        __syncthreads();
    }
    float amax = fmaxf(sb[0], 1e-5f);
    float sc = __fdiv_rn(127.f, amax);
    if (tid == 0) inva[row] = amax * (1.f / 127.f);
#pragma unroll
    for (int u = 0; u < 4; u++) {
        int a0 = max(-128, min(127, __float2int_rn(v[u].x * sc)));
        int a1 = max(-128, min(127, __float2int_rn(v[u].y * sc)));
        int a2 = max(-128, min(127, __float2int_rn(v[u].z * sc)));
        int a3 = max(-128, min(127, __float2int_rn(v[u].w * sc)));
        out[(size_t)row * KPACK + tid + u * 256] =
            (a0 & 255) | ((a1 & 255) << 8) | ((a2 & 255) << 16) | ((a3 & 255) << 24);
    }
}

// ---------------- int8 dp4a GEMM: C[m,n] = (sum_k A[m,k]*B[n,k]) * ws * inva[m] ----------------
// A: [MTOK, KPACK] packed int8, B: [N, KPACK] packed int8 (K-major both)
__global__ void __launch_bounds__(256) gemm_q8(const int* __restrict__ A, const int* __restrict__ Bw,
                                               const float* __restrict__ inva,
                                               const float* __restrict__ wscp,
                                               float* __restrict__ C, int N) {
    __shared__ int As[128][17];
    __shared__ int Bs[128][17];
    int tid = threadIdx.x;
    int ty = tid >> 4, tx = tid & 15;
    int m0 = blockIdx.x * 128, n0 = blockIdx.y * 128;
    int acc[8][8];
#pragma unroll
    for (int i = 0; i < 8; i++)
#pragma unroll
        for (int j = 0; j < 8; j++) acc[i][j] = 0;

    for (int k0 = 0; k0 < KPACK; k0 += 16) {
#pragma unroll
        for (int u = 0; u < 8; u++) {
            int idx = tid + u * 256;
            int r = idx >> 4, c = idx & 15;
            As[r][c] = A[(size_t)(m0 + r) * KPACK + k0 + c];
            Bs[r][c] = Bw[(size_t)(n0 + r) * KPACK + k0 + c];
        }
        __syncthreads();
#pragma unroll
        for (int kk = 0; kk < 16; kk++) {
            int a[8], b[8];
#pragma unroll
            for (int i = 0; i < 8; i++) a[i] = As[ty + 16 * i][kk];
#pragma unroll
            for (int j = 0; j < 8; j++) b[j] = Bs[tx + 16 * j][kk];
#pragma unroll
            for (int i = 0; i < 8; i++)
#pragma unroll
                for (int j = 0; j < 8; j++)
                    acc[i][j] = __dp4a(a[i], b[j], acc[i][j]);
        }
        __syncthreads();
    }
    float ws = *wscp;
#pragma unroll
    for (int i = 0; i < 8; i++) {
        int m = m0 + ty + 16 * i;
        float s = ws * inva[m];
#pragma unroll
        for (int j = 0; j < 8; j++)
            C[(size_t)m * N + n0 + tx + 16 * j] = (float)acc[i][j] * s;
    }
}

// ---------------- flash attention, base-2 softmax, causal, GQA 4:1 ----------------
// Q: [MTOK, 4096] (h*128+d), K/V: [MTOK, 1024] (kvh*128+d), O: [MTOK, 4096]
#define QPAD 132
__global__ void __launch_bounds__(256) attn_kernel(const float* __restrict__ Q,
                                                   const float* __restrict__ K,
                                                   const float* __restrict__ V,
                                                   float* __restrict__ O) {
    extern __shared__ float sm[];
    float* Qs = sm;                 // 64 x 132
    float* Ks = Qs + 64 * QPAD;     // 64 x 132
    float* Vs = Ks + 64 * QPAD;     // 64 x 132
    float* Ps = Vs + 64 * QPAD;     // 64 x 65

    const int qt = blockIdx.x, bh = blockIdx.y;
    const int b = bh >> 5, h = bh & 31, kvh = h >> 2;
    const int tid = threadIdx.x, ty = tid >> 4, tx = tid & 15;
    const float qsc = 0.08838834764831845f;  // 1/sqrt(128)
    const int q0 = b * SEQ + qt * 64;

#pragma unroll
    for (int u = 0; u < 8; u++) {
        int idx = tid + u * 256;          // float4 index, 0..2047
        int r = idx >> 5, c4 = idx & 31;
        float4 qv = *(const float4*)(Q + (size_t)(q0 + r) * HID + h * HD + c4 * 4);
        qv.x *= qsc; qv.y *= qsc; qv.z *= qsc; qv.w *= qsc;
        *(float4*)(Qs + r * QPAD + c4 * 4) = qv;
    }
    float mi[4], li[4], acc[4][8];
#pragma unroll
    for (int i = 0; i < 4; i++) {
        mi[i] = -1e30f; li[i] = 0.f;
#pragma unroll
        for (int j = 0; j < 8; j++) acc[i][j] = 0.f;
    }
    __syncthreads();

    for (int kt = 0; kt <= qt; kt++) {
        int k0r = b * SEQ + kt * 64;
#pragma unroll
        for (int u = 0; u < 8; u++) {
            int idx = tid + u * 256;
            int r = idx >> 5, c4 = idx & 31;
            *(float4*)(Ks + r * QPAD + c4 * 4) =
                *(const float4*)(K + (size_t)(k0r + r) * NKV + kvh * HD + c4 * 4);
            *(float4*)(Vs + r * QPAD + c4 * 4) =
                *(const float4*)(V + (size_t)(k0r + r) * NKV + kvh * HD + c4 * 4);
        }
        __syncthreads();

        float s[4][4];
#pragma unroll
        for (int i = 0; i < 4; i++)
#pragma unroll
            for (int j = 0; j < 4; j++) s[i][j] = 0.f;

        const float* qp0 = Qs + ty * QPAD;
        const float* kp0 = Ks + tx * QPAD;
#pragma unroll 4
        for (int d4 = 0; d4 < 32; d4++) {
            float4 a[4], bb[4];
#pragma unroll
            for (int i = 0; i < 4; i++) a[i] = *(const float4*)(qp0 + i * 16 * QPAD + d4 * 4);
#pragma unroll
            for (int j = 0; j < 4; j++) bb[j] = *(const float4*)(kp0 + j * 16 * QPAD + d4 * 4);
#pragma unroll
            for (int i = 0; i < 4; i++)
#pragma unroll
                for (int j = 0; j < 4; j++)
                    s[i][j] += a[i].x * bb[j].x + a[i].y * bb[j].y
                             + a[i].z * bb[j].z + a[i].w * bb[j].w;
        }
        if (kt == qt) {
#pragma unroll
            for (int i = 0; i < 4; i++)
#pragma unroll
                for (int j = 0; j < 4; j++)
                    if (tx + 16 * j > ty + 16 * i) s[i][j] = -1e30f;
        }
#pragma unroll
        for (int i = 0; i < 4; i++) {
            float mt = fmaxf(fmaxf(s[i][0], s[i][1]), fmaxf(s[i][2], s[i][3]));
            mt = fmaxf(mt, __shfl_xor_sync(0xffffffffu, mt, 8));
            mt = fmaxf(mt, __shfl_xor_sync(0xffffffffu, mt, 4));
            mt = fmaxf(mt, __shfl_xor_sync(0xffffffffu, mt, 2));
            mt = fmaxf(mt, __shfl_xor_sync(0xffffffffu, mt, 1));
            float mnew = fmaxf(mi[i], mt);
            float alpha = exp2f(mi[i] - mnew);
            mi[i] = mnew;
            float rs = 0.f;
#pragma unroll
            for (int j = 0; j < 4; j++) {
                float p = exp2f(s[i][j] - mnew);
                Ps[(ty + 16 * i) * 65 + tx + 16 * j] = p;
                rs += p;
            }
            rs += __shfl_xor_sync(0xffffffffu, rs, 8);
            rs += __shfl_xor_sync(0xffffffffu, rs, 4);
            rs += __shfl_xor_sync(0xffffffffu, rs, 2);
            rs += __shfl_xor_sync(0xffffffffu, rs, 1);
            li[i] = li[i] * alpha + rs;
#pragma unroll
            for (int jd = 0; jd < 8; jd++) acc[i][jd] *= alpha;
        }
        __syncthreads();
#pragma unroll 4
        for (int c = 0; c < 64; c++) {
            float4 v0 = *(const float4*)(Vs + c * QPAD + tx * 8);
            float4 v1 = *(const float4*)(Vs + c * QPAD + tx * 8 + 4);
#pragma unroll
            for (int i = 0; i < 4; i++) {
                float p = Ps[(ty + 16 * i) * 65 + c];
                acc[i][0] += p * v0.x; acc[i][1] += p * v0.y;
                acc[i][2] += p * v0.z; acc[i][3] += p * v0.w;
                acc[i][4] += p * v1.x; acc[i][5] += p * v1.y;
                acc[i][6] += p * v1.z; acc[i][7] += p * v1.w;
            }
        }
        __syncthreads();
    }
#pragma unroll
    for (int i = 0; i < 4; i++) {
        int r = q0 + ty + 16 * i;
        float inv = __fdiv_rn(1.f, li[i]);
        float4 o0 = make_float4(acc[i][0] * inv, acc[i][1] * inv, acc[i][2] * inv, acc[i][3] * inv);
        float4 o1 = make_float4(acc[i][4] * inv, acc[i][5] * inv, acc[i][6] * inv, acc[i][7] * inv);
        *(float4*)(O + (size_t)r * HID + h * HD + tx * 8) = o0;
        *(float4*)(O + (size_t)r * HID + h * HD + tx * 8 + 4) = o1;
    }
}

#define ATTN_SMEM ((3 * 64 * QPAD + 64 * 65) * 4)

// ---------------- launch ----------------
extern "C" void kernel_launch(void* const* d_in, const int* in_sizes, int n_in,
                              void* d_out, int out_size) {
    const float* hs = (const float*)d_in[0];
    // d_in[1] = attention_mask: exactly the causal -1e9 mask; handled analytically.
    const float* Wq = (const float*)d_in[2];
    const float* Wk = (const float*)d_in[3];
    const float* Wv = (const float*)d_in[4];
    const float* Wo = (const float*)d_in[5];

    void *p;
    cudaGetSymbolAddress(&p, g_xq);   int*   xq   = (int*)p;
    cudaGetSymbolAddress(&p, g_inva); float* inva = (float*)p;
    cudaGetSymbolAddress(&p, g_wqq);  int*   wqq  = (int*)p;
    cudaGetSymbolAddress(&p, g_wkq);  int*   wkq  = (int*)p;
    cudaGetSymbolAddress(&p, g_wvq);  int*   wvq  = (int*)p;
    cudaGetSymbolAddress(&p, g_woq);  int*   woq  = (int*)p;
    cudaGetSymbolAddress(&p, g_q);    float* q    = (float*)p;
    cudaGetSymbolAddress(&p, g_k);    float* k    = (float*)p;
    cudaGetSymbolAddress(&p, g_v);    float* v    = (float*)p;
    cudaGetSymbolAddress(&p, g_ao);   float* ao   = (float*)p;
    cudaGetSymbolAddress(&p, g_part); float* part = (float*)p;
    cudaGetSymbolAddress(&p, g_wsc);  float* wsc  = (float*)p;

    cudaFuncSetAttribute(attn_kernel, cudaFuncAttributeMaxDynamicSharedMemorySize, ATTN_SMEM);

    // weight scales (mean |W|)
    absmean_partial<<<1024, 256>>>(Wq, HID * HID, part + 0);
    absmean_partial<<<1024, 256>>>(Wk, NKV * HID, part + 1024);
    absmean_partial<<<1024, 256>>>(Wv, NKV * HID, part + 2048);
    absmean_partial<<<1024, 256>>>(Wo, HID * HID, part + 3072);
    wscale_final<<<4, 256>>>(part, wsc);

    // ternary weight quantization (packed int8x4)
    quant_w<<<(HID * KPACK + 255) / 256, 256>>>(Wq, HID * KPACK, wsc + 0, wqq);
    quant_w<<<(NKV * KPACK + 255) / 256, 256>>>(Wk, NKV * KPACK, wsc + 1, wkq);
    quant_w<<<(NKV * KPACK + 255) / 256, 256>>>(Wv, NKV * KPACK, wsc + 2, wvq);
    quant_w<<<(HID * KPACK + 255) / 256, 256>>>(Wo, HID * KPACK, wsc + 3, woq);

    // activation quant + QKV projections
    quant_a<<<MTOK, 256>>>(hs, xq, inva);
    gemm_q8<<<dim3(32, 32), 256>>>(xq, wqq, inva, wsc + 0, q, HID);
    gemm_q8<<<dim3(32, 8),  256>>>(xq, wkq, inva, wsc + 1, k, NKV);
    gemm_q8<<<dim3(32, 8),  256>>>(xq, wvq, inva, wsc + 2, v, NKV);

    // attention
    attn_kernel<<<dim3(32, 64), 256, ATTN_SMEM>>>(q, k, v, ao);

    // output projection
    quant_a<<<MTOK, 256>>>(ao, xq, inva);
    gemm_q8<<<dim3(32, 32), 256>>>(xq, woq, inva, wsc + 3, (float*)d_out, HID);
}

// round 3
// speedup vs baseline: 1.7883x; 1.7883x over previous
#include <cuda_runtime.h>
#include <cstdint>

#define SEQ   2048
#define MTOK  4096
#define HID   4096
#define KPACK 1024
#define NKV   1024
#define HD    128

// ---------------- scratch (device globals) ----------------
__device__ int   g_xq[MTOK * KPACK];        // packed int8 activations
__device__ float g_inva[MTOK];
__device__ int   g_wqq[HID * KPACK];
__device__ int   g_wkq[NKV * KPACK];
__device__ int   g_wvq[NKV * KPACK];
__device__ int   g_woq[HID * KPACK];
__device__ float g_q[(size_t)MTOK * HID];
__device__ float g_k[(size_t)MTOK * NKV];
__device__ float g_v[(size_t)MTOK * NKV];
__device__ float g_ao[(size_t)MTOK * HID];
__device__ float g_part[4 * 1024];
__device__ float g_wsc[4];

__device__ __forceinline__ uint32_t smem_u32(const void* p) {
    uint32_t a;
    asm("{ .reg .u64 t; cvta.to.shared.u64 t, %1; cvt.u32.u64 %0, t; }" : "=r"(a) : "l"(p));
    return a;
}
__device__ __forceinline__ void cp16(uint32_t dst, const void* src) {
    asm volatile("cp.async.cg.shared.global [%0], [%1], 16;" :: "r"(dst), "l"(src));
}
__device__ __forceinline__ void ldm_x4(uint32_t* r, uint32_t addr) {
    asm volatile("ldmatrix.sync.aligned.m8n8.x4.shared.b16 {%0,%1,%2,%3}, [%4];"
                 : "=r"(r[0]), "=r"(r[1]), "=r"(r[2]), "=r"(r[3]) : "r"(addr));
}
__device__ __forceinline__ void mma_s8(int* c, const uint32_t* a, uint32_t b0, uint32_t b1) {
    asm volatile("mma.sync.aligned.m16n8k32.row.col.s32.s8.s8.s32 "
                 "{%0,%1,%2,%3}, {%4,%5,%6,%7}, {%8,%9}, {%0,%1,%2,%3};"
                 : "+r"(c[0]), "+r"(c[1]), "+r"(c[2]), "+r"(c[3])
                 : "r"(a[0]), "r"(a[1]), "r"(a[2]), "r"(a[3]), "r"(b0), "r"(b1));
}

// ---------------- weight scale: mean(|W|), two-pass deterministic ----------------
__global__ void absmean_partial(const float* __restrict__ W, int n, float* __restrict__ part) {
    __shared__ float sb[256];
    int tid = threadIdx.x;
    float s = 0.f;
    for (long i = (long)blockIdx.x * 256 + tid; i < n; i += (long)gridDim.x * 256)
        s += fabsf(W[i]);
    sb[tid] = s; __syncthreads();
    for (int o = 128; o > 0; o >>= 1) {
        if (tid < o) sb[tid] += sb[tid + o];
        __syncthreads();
    }
    if (tid == 0) part[blockIdx.x] = sb[0];
}

__global__ void wscale_final(const float* __restrict__ part, float* __restrict__ wsc) {
    __shared__ float sb[256];
    int i = blockIdx.x, tid = threadIdx.x;
    float s = part[i * 1024 + tid] + part[i * 1024 + tid + 256]
            + part[i * 1024 + tid + 512] + part[i * 1024 + tid + 768];
    sb[tid] = s; __syncthreads();
    for (int o = 128; o > 0; o >>= 1) {
        if (tid < o) sb[tid] += sb[tid + o];
        __syncthreads();
    }
    if (tid == 0) {
        float n = (i == 0 || i == 3) ? 16777216.f : 4194304.f;
        wsc[i] = fmaxf(sb[0] / n, 1e-5f);
    }
}

// ---------------- ternary weight quant: clip(round(W/ws),-1,1) packed int8x4 ----------------
__global__ void quant_w(const float* __restrict__ W, int np, const float* __restrict__ wscp,
                        int* __restrict__ out) {
    int i = blockIdx.x * blockDim.x + threadIdx.x;
    if (i >= np) return;
    float ws = *wscp;
    float4 w = ((const float4*)W)[i];
    int v0 = min(1, max(-1, __float2int_rn(__fdiv_rn(w.x, ws))));
    int v1 = min(1, max(-1, __float2int_rn(__fdiv_rn(w.y, ws))));
    int v2 = min(1, max(-1, __float2int_rn(__fdiv_rn(w.z, ws))));
    int v3 = min(1, max(-1, __float2int_rn(__fdiv_rn(w.w, ws))));
    out[i] = (v0 & 255) | ((v1 & 255) << 8) | ((v2 & 255) << 16) | ((v3 & 255) << 24);
}

// ---------------- per-token int8 activation quant (absmax) ----------------
__global__ void quant_a(const float* __restrict__ X, int* __restrict__ out,
                        float* __restrict__ inva) {
    __shared__ float sb[256];
    int row = blockIdx.x, tid = threadIdx.x;
    const float4* xr = (const float4*)(X + (size_t)row * HID);
    float4 v[4];
    float am = 0.f;
#pragma unroll
    for (int u = 0; u < 4; u++) {
        v[u] = xr[tid + u * 256];
        am = fmaxf(am, fmaxf(fmaxf(fabsf(v[u].x), fabsf(v[u].y)),
                             fmaxf(fabsf(v[u].z), fabsf(v[u].w))));
    }
    sb[tid] = am; __syncthreads();
    for (int o = 128; o > 0; o >>= 1) {
        if (tid < o) sb[tid] = fmaxf(sb[tid], sb[tid + o]);
        __syncthreads();
    }
    float amax = fmaxf(sb[0], 1e-5f);
    float sc = __fdiv_rn(127.f, amax);
    if (tid == 0) inva[row] = amax * (1.f / 127.f);
#pragma unroll
    for (int u = 0; u < 4; u++) {
        int a0 = max(-128, min(127, __float2int_rn(v[u].x * sc)));
        int a1 = max(-128, min(127, __float2int_rn(v[u].y * sc)));
        int a2 = max(-128, min(127, __float2int_rn(v[u].z * sc)));
        int a3 = max(-128, min(127, __float2int_rn(v[u].w * sc)));
        out[(size_t)row * KPACK + tid + u * 256] =
            (a0 & 255) | ((a1 & 255) << 8) | ((a2 & 255) << 16) | ((a3 & 255) << 24);
    }
}

// ---------------- int8 mma.sync GEMM: C[m,n] = (sum_k A[m,k]*B[n,k]) * ws * inva[m] ----------------
// A: [MTOK][HID] int8 row-major, B: [N][HID] int8 row-major (K-contig both).
// CTA tile 128x128, 8 warps (warp tile 32x64), K-chunk 64, double-buffered cp.async.
// SMEM rows padded to 80B (stride 5*16B, coprime 8 -> conflict-free ldmatrix).
__global__ void __launch_bounds__(256) gemm_i8(const int8_t* __restrict__ A,
                                               const int8_t* __restrict__ Bw,
                                               const float* __restrict__ inva,
                                               const float* __restrict__ wscp,
                                               float* __restrict__ C, int N) {
    __shared__ int8_t As[2][128 * 80];
    __shared__ int8_t Bs[2][128 * 80];
    const int tid = threadIdx.x;
    const int lane = tid & 31, wid = tid >> 5;
    const int wm = wid & 3, wn = wid >> 2;        // warp m-offset 32*wm, n-offset 64*wn
    const int m0 = blockIdx.x * 128, n0 = blockIdx.y * 128;

    const uint32_t aB[2] = { smem_u32(As[0]), smem_u32(As[1]) };
    const uint32_t bB[2] = { smem_u32(Bs[0]), smem_u32(Bs[1]) };

    // per-thread load geometry: row = tid/2 (0..127), 32B half = tid&1
    const int lr = tid >> 1, lc = (tid & 1) * 32;
    const uint32_t sOff = lr * 80 + lc;
    const int8_t* Agp = A + (size_t)(m0 + lr) * HID + lc;
    const int8_t* Bgp = Bw + (size_t)(n0 + lr) * HID + lc;

    auto load = [&](int chunk, int st) {
        const int8_t* ag = Agp + chunk * 64;
        const int8_t* bg = Bgp + chunk * 64;
        cp16(aB[st] + sOff, ag);       cp16(aB[st] + sOff + 16, ag + 16);
        cp16(bB[st] + sOff, bg);       cp16(bB[st] + sOff + 16, bg + 16);
        asm volatile("cp.async.commit_group;" ::: "memory");
    };

    int acc[2][8][4];
#pragma unroll
    for (int i = 0; i < 2; i++)
#pragma unroll
        for (int j = 0; j < 8; j++)
#pragma unroll
            for (int t = 0; t < 4; t++) acc[i][j][t] = 0;

    // ldmatrix per-lane address pieces
    const uint32_t lmRow = (lane & 15) * 80 + (lane >> 4) * 16;
    const uint32_t aAddr0 = (wm * 32) * 80 + lmRow;          // + mt*16*80 + ks*32
    const uint32_t bAddr0 = (wn * 64) * 80 + lmRow;          // + ng*16*80 + ks*32

    const int NC = HID / 64;   // 64 chunks
    load(0, 0);
    load(1, 1);

    for (int c = 0; c < NC; c++) {
        const int st = c & 1;
        if (c < NC - 2) asm volatile("cp.async.wait_group 1;" ::: "memory");
        else            asm volatile("cp.async.wait_group 0;" ::: "memory");
        __syncthreads();

#pragma unroll
        for (int ks = 0; ks < 2; ks++) {
            uint32_t a[2][4], bf[4][4];
#pragma unroll
            for (int mt = 0; mt < 2; mt++)
                ldm_x4(a[mt], aB[st] + aAddr0 + mt * (16 * 80) + ks * 32);
#pragma unroll
            for (int ng = 0; ng < 4; ng++)
                ldm_x4(bf[ng], bB[st] + bAddr0 + ng * (16 * 80) + ks * 32);
#pragma unroll
            for (int mt = 0; mt < 2; mt++)
#pragma unroll
                for (int nt = 0; nt < 8; nt++)
                    mma_s8(acc[mt][nt], a[mt], bf[nt >> 1][nt & 1], bf[nt >> 1][2 + (nt & 1)]);
        }
        __syncthreads();
        if (c + 2 < NC) load(c + 2, st);
    }

    // epilogue
    const float wsv = *wscp;
#pragma unroll
    for (int mt = 0; mt < 2; mt++) {
        const int mlo = m0 + wm * 32 + mt * 16 + (lane >> 2);
        const float s0 = wsv * inva[mlo];
        const float s1 = wsv * inva[mlo + 8];
#pragma unroll
        for (int nt = 0; nt < 8; nt++) {
            const int n = n0 + wn * 64 + nt * 8 + (lane & 3) * 2;
            float2 lo = make_float2((float)acc[mt][nt][0] * s0, (float)acc[mt][nt][1] * s0);
            float2 hi = make_float2((float)acc[mt][nt][2] * s1, (float)acc[mt][nt][3] * s1);
            *(float2*)(C + (size_t)mlo * N + n) = lo;
            *(float2*)(C + (size_t)(mlo + 8) * N + n) = hi;
        }
    }
}

// ---------------- flash attention, base-2 softmax, causal, GQA 4:1 ----------------
#define QPAD 132
__global__ void __launch_bounds__(256) attn_kernel(const float* __restrict__ Q,
                                                   const float* __restrict__ K,
                                                   const float* __restrict__ V,
                                                   float* __restrict__ O) {
    extern __shared__ float sm[];
    float* Qs = sm;                 // 64 x 132
    float* Ks = Qs + 64 * QPAD;     // 64 x 132
    float* Vs = Ks + 64 * QPAD;     // 64 x 132
    float* Ps = Vs + 64 * QPAD;     // 64 x 65

    const int qt = blockIdx.x, bh = blockIdx.y;
    const int b = bh >> 5, h = bh & 31, kvh = h >> 2;
    const int tid = threadIdx.x, ty = tid >> 4, tx = tid & 15;
    const float qsc = 0.08838834764831845f;  // 1/sqrt(128)
    const int q0 = b * SEQ + qt * 64;

#pragma unroll
    for (int u = 0; u < 8; u++) {
        int idx = tid + u * 256;
        int r = idx >> 5, c4 = idx & 31;
        float4 qv = *(const float4*)(Q + (size_t)(q0 + r) * HID + h * HD + c4 * 4);
        qv.x *= qsc; qv.y *= qsc; qv.z *= qsc; qv.w *= qsc;
        *(float4*)(Qs + r * QPAD + c4 * 4) = qv;
    }
    float mi[4], li[4], acc[4][8];
#pragma unroll
    for (int i = 0; i < 4; i++) {
        mi[i] = -1e30f; li[i] = 0.f;
#pragma unroll
        for (int j = 0; j < 8; j++) acc[i][j] = 0.f;
    }
    __syncthreads();

    for (int kt = 0; kt <= qt; kt++) {
        int k0r = b * SEQ + kt * 64;
#pragma unroll
        for (int u = 0; u < 8; u++) {
            int idx = tid + u * 256;
            int r = idx >> 5, c4 = idx & 31;
            *(float4*)(Ks + r * QPAD + c4 * 4) =
                *(const float4*)(K + (size_t)(k0r + r) * NKV + kvh * HD + c4 * 4);
            *(float4*)(Vs + r * QPAD + c4 * 4) =
                *(const float4*)(V + (size_t)(k0r + r) * NKV + kvh * HD + c4 * 4);
        }
        __syncthreads();

        float s[4][4];
#pragma unroll
        for (int i = 0; i < 4; i++)
#pragma unroll
            for (int j = 0; j < 4; j++) s[i][j] = 0.f;

        const float* qp0 = Qs + ty * QPAD;
        const float* kp0 = Ks + tx * QPAD;
#pragma unroll 4
        for (int d4 = 0; d4 < 32; d4++) {
            float4 a[4], bb[4];
#pragma unroll
            for (int i = 0; i < 4; i++) a[i] = *(const float4*)(qp0 + i * 16 * QPAD + d4 * 4);
#pragma unroll
            for (int j = 0; j < 4; j++) bb[j] = *(const float4*)(kp0 + j * 16 * QPAD + d4 * 4);
#pragma unroll
            for (int i = 0; i < 4; i++)
#pragma unroll
                for (int j = 0; j < 4; j++)
                    s[i][j] += a[i].x * bb[j].x + a[i].y * bb[j].y
                             + a[i].z * bb[j].z + a[i].w * bb[j].w;
        }
        if (kt == qt) {
#pragma unroll
            for (int i = 0; i < 4; i++)
#pragma unroll
                for (int j = 0; j < 4; j++)
                    if (tx + 16 * j > ty + 16 * i) s[i][j] = -1e30f;
        }
#pragma unroll
        for (int i = 0; i < 4; i++) {
            float mt = fmaxf(fmaxf(s[i][0], s[i][1]), fmaxf(s[i][2], s[i][3]));
            mt = fmaxf(mt, __shfl_xor_sync(0xffffffffu, mt, 8));
            mt = fmaxf(mt, __shfl_xor_sync(0xffffffffu, mt, 4));
            mt = fmaxf(mt, __shfl_xor_sync(0xffffffffu, mt, 2));
            mt = fmaxf(mt, __shfl_xor_sync(0xffffffffu, mt, 1));
            float mnew = fmaxf(mi[i], mt);
            float alpha = exp2f(mi[i] - mnew);
            mi[i] = mnew;
            float rs = 0.f;
#pragma unroll
            for (int j = 0; j < 4; j++) {
                float p = exp2f(s[i][j] - mnew);
                Ps[(ty + 16 * i) * 65 + tx + 16 * j] = p;
                rs += p;
            }
            rs += __shfl_xor_sync(0xffffffffu, rs, 8);
            rs += __shfl_xor_sync(0xffffffffu, rs, 4);
            rs += __shfl_xor_sync(0xffffffffu, rs, 2);
            rs += __shfl_xor_sync(0xffffffffu, rs, 1);
            li[i] = li[i] * alpha + rs;
#pragma unroll
            for (int jd = 0; jd < 8; jd++) acc[i][jd] *= alpha;
        }
        __syncthreads();
#pragma unroll 4
        for (int c = 0; c < 64; c++) {
            float4 v0 = *(const float4*)(Vs + c * QPAD + tx * 8);
            float4 v1 = *(const float4*)(Vs + c * QPAD + tx * 8 + 4);
#pragma unroll
            for (int i = 0; i < 4; i++) {
                float p = Ps[(ty + 16 * i) * 65 + c];
                acc[i][0] += p * v0.x; acc[i][1] += p * v0.y;
                acc[i][2] += p * v0.z; acc[i][3] += p * v0.w;
                acc[i][4] += p * v1.x; acc[i][5] += p * v1.y;
                acc[i][6] += p * v1.z; acc[i][7] += p * v1.w;
            }
        }
        __syncthreads();
    }
#pragma unroll
    for (int i = 0; i < 4; i++) {
        int r = q0 + ty + 16 * i;
        float inv = __fdiv_rn(1.f, li[i]);
        float4 o0 = make_float4(acc[i][0] * inv, acc[i][1] * inv, acc[i][2] * inv, acc[i][3] * inv);
        float4 o1 = make_float4(acc[i][4] * inv, acc[i][5] * inv, acc[i][6] * inv, acc[i][7] * inv);
        *(float4*)(O + (size_t)r * HID + h * HD + tx * 8) = o0;
        *(float4*)(O + (size_t)r * HID + h * HD + tx * 8 + 4) = o1;
    }
}

#define ATTN_SMEM ((3 * 64 * QPAD + 64 * 65) * 4)

// ---------------- launch ----------------
extern "C" void kernel_launch(void* const* d_in, const int* in_sizes, int n_in,
                              void* d_out, int out_size) {
    const float* hs = (const float*)d_in[0];
    // d_in[1] = attention_mask: exactly the causal -1e9 mask; handled analytically.
    const float* Wq = (const float*)d_in[2];
    const float* Wk = (const float*)d_in[3];
    const float* Wv = (const float*)d_in[4];
    const float* Wo = (const float*)d_in[5];

    void* p;
    cudaGetSymbolAddress(&p, g_xq);   int*   xq   = (int*)p;
    cudaGetSymbolAddress(&p, g_inva); float* inva = (float*)p;
    cudaGetSymbolAddress(&p, g_wqq);  int*   wqq  = (int*)p;
    cudaGetSymbolAddress(&p, g_wkq);  int*   wkq  = (int*)p;
    cudaGetSymbolAddress(&p, g_wvq);  int*   wvq  = (int*)p;
    cudaGetSymbolAddress(&p, g_woq);  int*   woq  = (int*)p;
    cudaGetSymbolAddress(&p, g_q);    float* q    = (float*)p;
    cudaGetSymbolAddress(&p, g_k);    float* k    = (float*)p;
    cudaGetSymbolAddress(&p, g_v);    float* v    = (float*)p;
    cudaGetSymbolAddress(&p, g_ao);   float* ao   = (float*)p;
    cudaGetSymbolAddress(&p, g_part); float* part = (float*)p;
    cudaGetSymbolAddress(&p, g_wsc);  float* wsc  = (float*)p;

    cudaFuncSetAttribute(attn_kernel, cudaFuncAttributeMaxDynamicSharedMemorySize, ATTN_SMEM);

    // weight scales (mean |W|)
    absmean_partial<<<1024, 256>>>(Wq, HID * HID, part + 0);
    absmean_partial<<<1024, 256>>>(Wk, NKV * HID, part + 1024);
    absmean_partial<<<1024, 256>>>(Wv, NKV * HID, part + 2048);
    absmean_partial<<<1024, 256>>>(Wo, HID * HID, part + 3072);
    wscale_final<<<4, 256>>>(part, wsc);

    // ternary weight quantization (packed int8x4)
    quant_w<<<(HID * KPACK + 255) / 256, 256>>>(Wq, HID * KPACK, wsc + 0, wqq);
    quant_w<<<(NKV * KPACK + 255) / 256, 256>>>(Wk, NKV * KPACK, wsc + 1, wkq);
    quant_w<<<(NKV * KPACK + 255) / 256, 256>>>(Wv, NKV * KPACK, wsc + 2, wvq);
    quant_w<<<(HID * KPACK + 255) / 256, 256>>>(Wo, HID * KPACK, wsc + 3, woq);

    // activation quant + QKV projections (int8 mma.sync)
    quant_a<<<MTOK, 256>>>(hs, xq, inva);
    gemm_i8<<<dim3(32, 32), 256>>>((const int8_t*)xq, (const int8_t*)wqq, inva, wsc + 0, q, HID);
    gemm_i8<<<dim3(32, 8),  256>>>((const int8_t*)xq, (const int8_t*)wkq, inva, wsc + 1, k, NKV);
    gemm_i8<<<dim3(32, 8),  256>>>((const int8_t*)xq, (const int8_t*)wvq, inva, wsc + 2, v, NKV);

    // attention
    attn_kernel<<<dim3(32, 64), 256, ATTN_SMEM>>>(q, k, v, ao);

    // output projection
    quant_a<<<MTOK, 256>>>(ao, xq, inva);
    gemm_i8<<<dim3(32, 32), 256>>>((const int8_t*)xq, (const int8_t*)woq, inva, wsc + 3,
                                   (float*)d_out, HID);
}

// round 4
// speedup vs baseline: 2.6848x; 1.5013x over previous
#include <cuda_runtime.h>
#include <cuda_bf16.h>
#include <cstdint>

#define SEQ   2048
#define MTOK  4096
#define HID   4096
#define KPACK 1024
#define NKV   1024
#define HD    128

// ---------------- scratch (device globals) ----------------
__device__ int   g_xq[MTOK * KPACK];        // packed int8 activations
__device__ float g_inva[MTOK];
__device__ int   g_wqq[HID * KPACK];
__device__ int   g_wkq[NKV * KPACK];
__device__ int   g_wvq[NKV * KPACK];
__device__ int   g_woq[NKV * 0 + HID * KPACK];
__device__ float g_q[(size_t)MTOK * HID];
__device__ float g_k[(size_t)MTOK * NKV];
__device__ float g_v[(size_t)MTOK * NKV];
__device__ float g_ao[(size_t)MTOK * HID];
__device__ float g_part[4 * 1024];
__device__ float g_wsc[4];

__device__ __forceinline__ uint32_t smem_u32(const void* p) {
    uint32_t a;
    asm("{ .reg .u64 t; cvta.to.shared.u64 t, %1; cvt.u32.u64 %0, t; }" : "=r"(a) : "l"(p));
    return a;
}
__device__ __forceinline__ void cp16(uint32_t dst, const void* src) {
    asm volatile("cp.async.cg.shared.global [%0], [%1], 16;" :: "r"(dst), "l"(src));
}
__device__ __forceinline__ void ldm_x4(uint32_t* r, uint32_t addr) {
    asm volatile("ldmatrix.sync.aligned.m8n8.x4.shared.b16 {%0,%1,%2,%3}, [%4];"
                 : "=r"(r[0]), "=r"(r[1]), "=r"(r[2]), "=r"(r[3]) : "r"(addr));
}
__device__ __forceinline__ void ldm_x4t(uint32_t* r, uint32_t addr) {
    asm volatile("ldmatrix.sync.aligned.m8n8.x4.trans.shared.b16 {%0,%1,%2,%3}, [%4];"
                 : "=r"(r[0]), "=r"(r[1]), "=r"(r[2]), "=r"(r[3]) : "r"(addr));
}
__device__ __forceinline__ void mma_s8(int* c, const uint32_t* a, uint32_t b0, uint32_t b1) {
    asm volatile("mma.sync.aligned.m16n8k32.row.col.s32.s8.s8.s32 "
                 "{%0,%1,%2,%3}, {%4,%5,%6,%7}, {%8,%9}, {%0,%1,%2,%3};"
                 : "+r"(c[0]), "+r"(c[1]), "+r"(c[2]), "+r"(c[3])
                 : "r"(a[0]), "r"(a[1]), "r"(a[2]), "r"(a[3]), "r"(b0), "r"(b1));
}
__device__ __forceinline__ void mma_bf16(float* c, const uint32_t* a, uint32_t b0, uint32_t b1) {
    asm volatile("mma.sync.aligned.m16n8k16.row.col.f32.bf16.bf16.f32 "
                 "{%0,%1,%2,%3}, {%4,%5,%6,%7}, {%8,%9}, {%0,%1,%2,%3};"
                 : "+f"(c[0]), "+f"(c[1]), "+f"(c[2]), "+f"(c[3])
                 : "r"(a[0]), "r"(a[1]), "r"(a[2]), "r"(a[3]), "r"(b0), "r"(b1));
}
__device__ __forceinline__ uint32_t pack2(__nv_bfloat16 x, __nv_bfloat16 y) {
    __nv_bfloat162 t = __halves2bfloat162(x, y);
    return *(uint32_t*)&t;
}

// ---------------- weight scale: mean(|W|), two-pass deterministic ----------------
__global__ void absmean_partial(const float* __restrict__ W, int n, float* __restrict__ part) {
    __shared__ float sb[256];
    int tid = threadIdx.x;
    float s = 0.f;
    for (long i = (long)blockIdx.x * 256 + tid; i < n; i += (long)gridDim.x * 256)
        s += fabsf(W[i]);
    sb[tid] = s; __syncthreads();
    for (int o = 128; o > 0; o >>= 1) {
        if (tid < o) sb[tid] += sb[tid + o];
        __syncthreads();
    }
    if (tid == 0) part[blockIdx.x] = sb[0];
}

__global__ void wscale_final(const float* __restrict__ part, float* __restrict__ wsc) {
    __shared__ float sb[256];
    int i = blockIdx.x, tid = threadIdx.x;
    float s = part[i * 1024 + tid] + part[i * 1024 + tid + 256]
            + part[i * 1024 + tid + 512] + part[i * 1024 + tid + 768];
    sb[tid] = s; __syncthreads();
    for (int o = 128; o > 0; o >>= 1) {
        if (tid < o) sb[tid] += sb[tid + o];
        __syncthreads();
    }
    if (tid == 0) {
        float n = (i == 0 || i == 3) ? 16777216.f : 4194304.f;
        wsc[i] = fmaxf(sb[0] / n, 1e-5f);
    }
}

// ---------------- ternary weight quant: clip(round(W/ws),-1,1) packed int8x4 ----------------
__global__ void quant_w(const float* __restrict__ W, int np, const float* __restrict__ wscp,
                        int* __restrict__ out) {
    int i = blockIdx.x * blockDim.x + threadIdx.x;
    if (i >= np) return;
    float ws = *wscp;
    float4 w = ((const float4*)W)[i];
    int v0 = min(1, max(-1, __float2int_rn(__fdiv_rn(w.x, ws))));
    int v1 = min(1, max(-1, __float2int_rn(__fdiv_rn(w.y, ws))));
    int v2 = min(1, max(-1, __float2int_rn(__fdiv_rn(w.z, ws))));
    int v3 = min(1, max(-1, __float2int_rn(__fdiv_rn(w.w, ws))));
    out[i] = (v0 & 255) | ((v1 & 255) << 8) | ((v2 & 255) << 16) | ((v3 & 255) << 24);
}

// ---------------- per-token int8 activation quant (absmax) ----------------
__global__ void quant_a(const float* __restrict__ X, int* __restrict__ out,
                        float* __restrict__ inva) {
    __shared__ float sb[256];
    int row = blockIdx.x, tid = threadIdx.x;
    const float4* xr = (const float4*)(X + (size_t)row * HID);
    float4 v[4];
    float am = 0.f;
#pragma unroll
    for (int u = 0; u < 4; u++) {
        v[u] = xr[tid + u * 256];
        am = fmaxf(am, fmaxf(fmaxf(fabsf(v[u].x), fabsf(v[u].y)),
                             fmaxf(fabsf(v[u].z), fabsf(v[u].w))));
    }
    sb[tid] = am; __syncthreads();
    for (int o = 128; o > 0; o >>= 1) {
        if (tid < o) sb[tid] = fmaxf(sb[tid], sb[tid + o]);
        __syncthreads();
    }
    float amax = fmaxf(sb[0], 1e-5f);
    float sc = __fdiv_rn(127.f, amax);
    if (tid == 0) inva[row] = amax * (1.f / 127.f);
#pragma unroll
    for (int u = 0; u < 4; u++) {
        int a0 = max(-128, min(127, __float2int_rn(v[u].x * sc)));
        int a1 = max(-128, min(127, __float2int_rn(v[u].y * sc)));
        int a2 = max(-128, min(127, __float2int_rn(v[u].z * sc)));
        int a3 = max(-128, min(127, __float2int_rn(v[u].w * sc)));
        out[(size_t)row * KPACK + tid + u * 256] =
            (a0 & 255) | ((a1 & 255) << 8) | ((a2 & 255) << 16) | ((a3 & 255) << 24);
    }
}

// ---------------- int8 mma.sync GEMM ----------------
__global__ void __launch_bounds__(256) gemm_i8(const int8_t* __restrict__ A,
                                               const int8_t* __restrict__ Bw,
                                               const float* __restrict__ inva,
                                               const float* __restrict__ wscp,
                                               float* __restrict__ C, int N) {
    __shared__ int8_t As[2][128 * 80];
    __shared__ int8_t Bs[2][128 * 80];
    const int tid = threadIdx.x;
    const int lane = tid & 31, wid = tid >> 5;
    const int wm = wid & 3, wn = wid >> 2;
    const int m0 = blockIdx.x * 128, n0 = blockIdx.y * 128;

    const uint32_t aB[2] = { smem_u32(As[0]), smem_u32(As[1]) };
    const uint32_t bB[2] = { smem_u32(Bs[0]), smem_u32(Bs[1]) };

    const int lr = tid >> 1, lc = (tid & 1) * 32;
    const uint32_t sOff = lr * 80 + lc;
    const int8_t* Agp = A + (size_t)(m0 + lr) * HID + lc;
    const int8_t* Bgp = Bw + (size_t)(n0 + lr) * HID + lc;

    auto load = [&](int chunk, int st) {
        const int8_t* ag = Agp + chunk * 64;
        const int8_t* bg = Bgp + chunk * 64;
        cp16(aB[st] + sOff, ag);       cp16(aB[st] + sOff + 16, ag + 16);
        cp16(bB[st] + sOff, bg);       cp16(bB[st] + sOff + 16, bg + 16);
        asm volatile("cp.async.commit_group;" ::: "memory");
    };

    int acc[2][8][4];
#pragma unroll
    for (int i = 0; i < 2; i++)
#pragma unroll
        for (int j = 0; j < 8; j++)
#pragma unroll
            for (int t = 0; t < 4; t++) acc[i][j][t] = 0;

    const uint32_t lmRow = (lane & 15) * 80 + (lane >> 4) * 16;
    const uint32_t aAddr0 = (wm * 32) * 80 + lmRow;
    const uint32_t bAddr0 = (wn * 64) * 80 + lmRow;

    const int NC = HID / 64;
    load(0, 0);
    load(1, 1);

    for (int c = 0; c < NC; c++) {
        const int st = c & 1;
        if (c < NC - 2) asm volatile("cp.async.wait_group 1;" ::: "memory");
        else            asm volatile("cp.async.wait_group 0;" ::: "memory");
        __syncthreads();

#pragma unroll
        for (int ks = 0; ks < 2; ks++) {
            uint32_t a[2][4], bf[4][4];
#pragma unroll
            for (int mt = 0; mt < 2; mt++)
                ldm_x4(a[mt], aB[st] + aAddr0 + mt * (16 * 80) + ks * 32);
#pragma unroll
            for (int ng = 0; ng < 4; ng++)
                ldm_x4(bf[ng], bB[st] + bAddr0 + ng * (16 * 80) + ks * 32);
#pragma unroll
            for (int mt = 0; mt < 2; mt++)
#pragma unroll
                for (int nt = 0; nt < 8; nt++)
                    mma_s8(acc[mt][nt], a[mt], bf[nt >> 1][nt & 1], bf[nt >> 1][2 + (nt & 1)]);
        }
        __syncthreads();
        if (c + 2 < NC) load(c + 2, st);
    }

    const float wsv = *wscp;
#pragma unroll
    for (int mt = 0; mt < 2; mt++) {
        const int mlo = m0 + wm * 32 + mt * 16 + (lane >> 2);
        const float s0 = wsv * inva[mlo];
        const float s1 = wsv * inva[mlo + 8];
#pragma unroll
        for (int nt = 0; nt < 8; nt++) {
            const int n = n0 + wn * 64 + nt * 8 + (lane & 3) * 2;
            float2 lo = make_float2((float)acc[mt][nt][0] * s0, (float)acc[mt][nt][1] * s0);
            float2 hi = make_float2((float)acc[mt][nt][2] * s1, (float)acc[mt][nt][3] * s1);
            *(float2*)(C + (size_t)mlo * N + n) = lo;
            *(float2*)(C + (size_t)(mlo + 8) * N + n) = hi;
        }
    }
}

// ---------------- tensor-core flash attention, 3x-bf16 split, base-2 softmax ----------------
// CTA: 64 q-rows x 64 k-cols, 4 warps (warp = m16). Q/K/V fp32 -> (hi,lo) bf16 in smem.
#define AP 136                         // smem pitch in bf16 elems (272B = 17*16B)
#define ATTN_SMEM (6 * 64 * AP * 2)    // Qh,Ql,Kh,Kl,Vh,Vl

__device__ __forceinline__ void bfsplit4(__nv_bfloat16* Hi, __nv_bfloat16* Lo, int off, float4 x) {
    __nv_bfloat16 h0 = __float2bfloat16(x.x), h1 = __float2bfloat16(x.y);
    __nv_bfloat16 h2 = __float2bfloat16(x.z), h3 = __float2bfloat16(x.w);
    __nv_bfloat16 l0 = __float2bfloat16(x.x - __bfloat162float(h0));
    __nv_bfloat16 l1 = __float2bfloat16(x.y - __bfloat162float(h1));
    __nv_bfloat16 l2 = __float2bfloat16(x.z - __bfloat162float(h2));
    __nv_bfloat16 l3 = __float2bfloat16(x.w - __bfloat162float(h3));
    *(__nv_bfloat162*)(Hi + off)     = __halves2bfloat162(h0, h1);
    *(__nv_bfloat162*)(Hi + off + 2) = __halves2bfloat162(h2, h3);
    *(__nv_bfloat162*)(Lo + off)     = __halves2bfloat162(l0, l1);
    *(__nv_bfloat162*)(Lo + off + 2) = __halves2bfloat162(l2, l3);
}

__global__ void __launch_bounds__(128) attn_mma(const float* __restrict__ Q,
                                                const float* __restrict__ K,
                                                const float* __restrict__ V,
                                                float* __restrict__ O) {
    extern __shared__ __nv_bfloat16 sm[];
    __nv_bfloat16* Qh = sm;
    __nv_bfloat16* Ql = Qh + 64 * AP;
    __nv_bfloat16* Kh = Ql + 64 * AP;
    __nv_bfloat16* Kl = Kh + 64 * AP;
    __nv_bfloat16* Vh = Kl + 64 * AP;
    __nv_bfloat16* Vl = Vh + 64 * AP;

    const int qt = 31 - blockIdx.x;          // longest diagonals first
    const int bh = blockIdx.y;
    const int b = bh >> 5, h = bh & 31, kvh = h >> 2;
    const int tid = threadIdx.x, warp = tid >> 5, lane = tid & 31;
    const int q0 = b * SEQ + qt * 64;
    const float qsc = 0.08838834764831845f;  // 1/sqrt(128)

    // load + split Q (scaled)
    for (int i = tid; i < 64 * 32; i += 128) {
        int r = i >> 5, c4 = i & 31;
        float4 x = *(const float4*)(Q + (size_t)(q0 + r) * HID + h * HD + c4 * 4);
        x.x *= qsc; x.y *= qsc; x.z *= qsc; x.w *= qsc;
        bfsplit4(Qh, Ql, r * AP + c4 * 4, x);
    }

    const uint32_t sQh = smem_u32(Qh), sQl = smem_u32(Ql);
    const uint32_t sKh = smem_u32(Kh), sKl = smem_u32(Kl);
    const uint32_t sVh = smem_u32(Vh), sVl = smem_u32(Vl);

    // ldmatrix lane address offsets (bytes)
    const uint32_t aOff  = ((warp * 16 + (lane & 15)) * AP + (lane >> 4) * 8) * 2;
    const uint32_t bkOff = ((((lane & 7) + ((lane >> 4) & 1) * 8)) * AP + ((lane >> 3) & 1) * 8) * 2;
    const uint32_t bvOff = (((lane & 7) + ((lane >> 3) & 1) * 8)) * AP * 2 + ((lane >> 4) & 1) * 16;

    float o[16][4];
#pragma unroll
    for (int nb = 0; nb < 16; nb++)
#pragma unroll
        for (int t = 0; t < 4; t++) o[nb][t] = 0.f;
    float mi0 = -1e30f, mi1 = -1e30f, l0 = 0.f, l1 = 0.f;

    for (int kt = 0; kt <= qt; kt++) {
        __syncthreads();   // previous tile fully consumed
        const int k0r = b * SEQ + kt * 64;
        for (int i = tid; i < 64 * 32; i += 128) {
            int r = i >> 5, c4 = i & 31;
            float4 kx = *(const float4*)(K + (size_t)(k0r + r) * NKV + kvh * HD + c4 * 4);
            bfsplit4(Kh, Kl, r * AP + c4 * 4, kx);
            float4 vx = *(const float4*)(V + (size_t)(k0r + r) * NKV + kvh * HD + c4 * 4);
            bfsplit4(Vh, Vl, r * AP + c4 * 4, vx);
        }
        __syncthreads();

        // S = Q K^T  (3-term bf16 split)
        float s[8][4];
#pragma unroll
        for (int j = 0; j < 8; j++)
#pragma unroll
            for (int t = 0; t < 4; t++) s[j][t] = 0.f;

#pragma unroll
        for (int kk = 0; kk < 8; kk++) {
            uint32_t ah[4], al[4];
            ldm_x4(ah, sQh + aOff + kk * 32);
            ldm_x4(al, sQl + aOff + kk * 32);
#pragma unroll
            for (int p = 0; p < 4; p++) {
                uint32_t bh_[4], bl_[4];
                ldm_x4(bh_, sKh + bkOff + p * (16 * AP * 2) + kk * 32);
                ldm_x4(bl_, sKl + bkOff + p * (16 * AP * 2) + kk * 32);
                mma_bf16(s[2 * p],     ah, bh_[0], bh_[1]);
                mma_bf16(s[2 * p],     ah, bl_[0], bl_[1]);
                mma_bf16(s[2 * p],     al, bh_[0], bh_[1]);
                mma_bf16(s[2 * p + 1], ah, bh_[2], bh_[3]);
                mma_bf16(s[2 * p + 1], ah, bl_[2], bl_[3]);
                mma_bf16(s[2 * p + 1], al, bh_[2], bh_[3]);
            }
        }

        if (kt == qt) {     // causal mask inside diagonal tile
            const int r0 = warp * 16 + (lane >> 2);
#pragma unroll
            for (int j = 0; j < 8; j++) {
                int c0 = j * 8 + (lane & 3) * 2;
                if (c0 > r0)          s[j][0] = -1e30f;
                if (c0 + 1 > r0)      s[j][1] = -1e30f;
                if (c0 > r0 + 8)      s[j][2] = -1e30f;
                if (c0 + 1 > r0 + 8)  s[j][3] = -1e30f;
            }
        }

        // base-2 online softmax
        float mt0 = -1e30f, mt1 = -1e30f;
#pragma unroll
        for (int j = 0; j < 8; j++) {
            mt0 = fmaxf(mt0, fmaxf(s[j][0], s[j][1]));
            mt1 = fmaxf(mt1, fmaxf(s[j][2], s[j][3]));
        }
        mt0 = fmaxf(mt0, __shfl_xor_sync(0xffffffffu, mt0, 1));
        mt0 = fmaxf(mt0, __shfl_xor_sync(0xffffffffu, mt0, 2));
        mt1 = fmaxf(mt1, __shfl_xor_sync(0xffffffffu, mt1, 1));
        mt1 = fmaxf(mt1, __shfl_xor_sync(0xffffffffu, mt1, 2));
        float mn0 = fmaxf(mi0, mt0), mn1 = fmaxf(mi1, mt1);
        float al0 = exp2f(mi0 - mn0), al1 = exp2f(mi1 - mn1);
        mi0 = mn0; mi1 = mn1;
        float rs0 = 0.f, rs1 = 0.f;
#pragma unroll
        for (int j = 0; j < 8; j++) {
            s[j][0] = exp2f(s[j][0] - mn0); rs0 += s[j][0];
            s[j][1] = exp2f(s[j][1] - mn0); rs0 += s[j][1];
            s[j][2] = exp2f(s[j][2] - mn1); rs1 += s[j][2];
            s[j][3] = exp2f(s[j][3] - mn1); rs1 += s[j][3];
        }
        rs0 += __shfl_xor_sync(0xffffffffu, rs0, 1);
        rs0 += __shfl_xor_sync(0xffffffffu, rs0, 2);
        rs1 += __shfl_xor_sync(0xffffffffu, rs1, 1);
        rs1 += __shfl_xor_sync(0xffffffffu, rs1, 2);
        l0 = l0 * al0 + rs0;
        l1 = l1 * al1 + rs1;
#pragma unroll
        for (int nb = 0; nb < 16; nb++) {
            o[nb][0] *= al0; o[nb][1] *= al0;
            o[nb][2] *= al1; o[nb][3] *= al1;
        }

        // O += P V  (P split hi/lo in registers; A-frag from C-frag layout)
#pragma unroll
        for (int kk = 0; kk < 4; kk++) {
            uint32_t ah[4], al_[4];
#pragma unroll
            for (int half = 0; half < 2; half++) {
                const float* sp = s[2 * kk + half];
                __nv_bfloat16 h0 = __float2bfloat16(sp[0]), h1 = __float2bfloat16(sp[1]);
                __nv_bfloat16 h2 = __float2bfloat16(sp[2]), h3 = __float2bfloat16(sp[3]);
                ah[2 * half]     = pack2(h0, h1);
                ah[2 * half + 1] = pack2(h2, h3);
                al_[2 * half]     = pack2(__float2bfloat16(sp[0] - __bfloat162float(h0)),
                                          __float2bfloat16(sp[1] - __bfloat162float(h1)));
                al_[2 * half + 1] = pack2(__float2bfloat16(sp[2] - __bfloat162float(h2)),
                                          __float2bfloat16(sp[3] - __bfloat162float(h3)));
            }
#pragma unroll
            for (int j = 0; j < 8; j++) {
                uint32_t bh_[4], bl_[4];
                ldm_x4t(bh_, sVh + bvOff + kk * (16 * AP * 2) + j * 32);
                ldm_x4t(bl_, sVl + bvOff + kk * (16 * AP * 2) + j * 32);
                mma_bf16(o[2 * j],     ah,  bh_[0], bh_[1]);
                mma_bf16(o[2 * j],     ah,  bl_[0], bl_[1]);
                mma_bf16(o[2 * j],     al_, bh_[0], bh_[1]);
                mma_bf16(o[2 * j + 1], ah,  bh_[2], bh_[3]);
                mma_bf16(o[2 * j + 1], ah,  bl_[2], bl_[3]);
                mma_bf16(o[2 * j + 1], al_, bh_[2], bh_[3]);
            }
        }
    }

    // epilogue
    const float inv0 = __fdiv_rn(1.f, l0), inv1 = __fdiv_rn(1.f, l1);
    const int r0 = q0 + warp * 16 + (lane >> 2);
    const int cbase = h * HD + (lane & 3) * 2;
#pragma unroll
    for (int nb = 0; nb < 16; nb++) {
        *(float2*)(O + (size_t)r0 * HID + cbase + nb * 8) =
            make_float2(o[nb][0] * inv0, o[nb][1] * inv0);
        *(float2*)(O + (size_t)(r0 + 8) * HID + cbase + nb * 8) =
            make_float2(o[nb][2] * inv1, o[nb][3] * inv1);
    }
}

// ---------------- launch ----------------
extern "C" void kernel_launch(void* const* d_in, const int* in_sizes, int n_in,
                              void* d_out, int out_size) {
    const float* hs = (const float*)d_in[0];
    // d_in[1] = attention_mask: exactly the causal -1e9 mask; handled analytically.
    const float* Wq = (const float*)d_in[2];
    const float* Wk = (const float*)d_in[3];
    const float* Wv = (const float*)d_in[4];
    const float* Wo = (const float*)d_in[5];

    void* p;
    cudaGetSymbolAddress(&p, g_xq);   int*   xq   = (int*)p;
    cudaGetSymbolAddress(&p, g_inva); float* inva = (float*)p;
    cudaGetSymbolAddress(&p, g_wqq);  int*   wqq  = (int*)p;
    cudaGetSymbolAddress(&p, g_wkq);  int*   wkq  = (int*)p;
    cudaGetSymbolAddress(&p, g_wvq);  int*   wvq  = (int*)p;
    cudaGetSymbolAddress(&p, g_woq);  int*   woq  = (int*)p;
    cudaGetSymbolAddress(&p, g_q);    float* q    = (float*)p;
    cudaGetSymbolAddress(&p, g_k);    float* k    = (float*)p;
    cudaGetSymbolAddress(&p, g_v);    float* v    = (float*)p;
    cudaGetSymbolAddress(&p, g_ao);   float* ao   = (float*)p;
    cudaGetSymbolAddress(&p, g_part); float* part = (float*)p;
    cudaGetSymbolAddress(&p, g_wsc);  float* wsc  = (float*)p;

    cudaFuncSetAttribute(attn_mma, cudaFuncAttributeMaxDynamicSharedMemorySize, ATTN_SMEM);

    // weight scales (mean |W|)
    absmean_partial<<<1024, 256>>>(Wq, HID * HID, part + 0);
    absmean_partial<<<1024, 256>>>(Wk, NKV * HID, part + 1024);
    absmean_partial<<<1024, 256>>>(Wv, NKV * HID, part + 2048);
    absmean_partial<<<1024, 256>>>(Wo, HID * HID, part + 3072);
    wscale_final<<<4, 256>>>(part, wsc);

    // ternary weight quantization (packed int8x4)
    quant_w<<<(HID * KPACK + 255) / 256, 256>>>(Wq, HID * KPACK, wsc + 0, wqq);
    quant_w<<<(NKV * KPACK + 255) / 256, 256>>>(Wk, NKV * KPACK, wsc + 1, wkq);
    quant_w<<<(NKV * KPACK + 255) / 256, 256>>>(Wv, NKV * KPACK, wsc + 2, wvq);
    quant_w<<<(HID * KPACK + 255) / 256, 256>>>(Wo, HID * KPACK, wsc + 3, woq);

    // activation quant + QKV projections (int8 mma.sync)
    quant_a<<<MTOK, 256>>>(hs, xq, inva);
    gemm_i8<<<dim3(32, 32), 256>>>((const int8_t*)xq, (const int8_t*)wqq, inva, wsc + 0, q, HID);
    gemm_i8<<<dim3(32, 8),  256>>>((const int8_t*)xq, (const int8_t*)wkq, inva, wsc + 1, k, NKV);
    gemm_i8<<<dim3(32, 8),  256>>>((const int8_t*)xq, (const int8_t*)wvq, inva, wsc + 2, v, NKV);

    // tensor-core flash attention
    attn_mma<<<dim3(32, 64), 128, ATTN_SMEM>>>(q, k, v, ao);

    // output projection
    quant_a<<<MTOK, 256>>>(ao, xq, inva);
    gemm_i8<<<dim3(32, 32), 256>>>((const int8_t*)xq, (const int8_t*)woq, inva, wsc + 3,
                                   (float*)d_out, HID);
}

// round 5
// speedup vs baseline: 2.8971x; 1.0791x over previous
#include <cuda_runtime.h>
#include <cuda_bf16.h>
#include <cstdint>

#define SEQ   2048
#define MTOK  4096
#define HID   4096
#define KPACK 1024
#define NKV   1024
#define HD    128
#define NQKV  6144          // fused projection width
#define QSC   0.08838834764831845f   // 1/sqrt(128)

// ---------------- scratch (device globals) ----------------
__device__ int   g_xq[MTOK * KPACK];          // packed int8 activations
__device__ float g_inva[MTOK];
__device__ int   g_wqkv[NQKV * KPACK];        // fused ternary Q|K|V weights
__device__ int   g_woq[HID * KPACK];
__device__ __nv_bfloat16 g_qh[(size_t)MTOK * HID];
__device__ __nv_bfloat16 g_ql[(size_t)MTOK * HID];
__device__ __nv_bfloat16 g_kh[(size_t)MTOK * NKV];
__device__ __nv_bfloat16 g_kl[(size_t)MTOK * NKV];
__device__ __nv_bfloat16 g_vh[(size_t)MTOK * NKV];
__device__ __nv_bfloat16 g_vl[(size_t)MTOK * NKV];
__device__ float g_ao[(size_t)MTOK * HID];
__device__ float g_part[4 * 1024];
__device__ float g_wsc[4];

__device__ __forceinline__ uint32_t smem_u32(const void* p) {
    uint32_t a;
    asm("{ .reg .u64 t; cvta.to.shared.u64 t, %1; cvt.u32.u64 %0, t; }" : "=r"(a) : "l"(p));
    return a;
}
__device__ __forceinline__ void cp16(uint32_t dst, const void* src) {
    asm volatile("cp.async.cg.shared.global [%0], [%1], 16;" :: "r"(dst), "l"(src));
}
__device__ __forceinline__ void ldm_x4(uint32_t* r, uint32_t addr) {
    asm volatile("ldmatrix.sync.aligned.m8n8.x4.shared.b16 {%0,%1,%2,%3}, [%4];"
                 : "=r"(r[0]), "=r"(r[1]), "=r"(r[2]), "=r"(r[3]) : "r"(addr));
}
__device__ __forceinline__ void ldm_x4t(uint32_t* r, uint32_t addr) {
    asm volatile("ldmatrix.sync.aligned.m8n8.x4.trans.shared.b16 {%0,%1,%2,%3}, [%4];"
                 : "=r"(r[0]), "=r"(r[1]), "=r"(r[2]), "=r"(r[3]) : "r"(addr));
}
__device__ __forceinline__ void mma_s8(int* c, const uint32_t* a, uint32_t b0, uint32_t b1) {
    asm volatile("mma.sync.aligned.m16n8k32.row.col.s32.s8.s8.s32 "
                 "{%0,%1,%2,%3}, {%4,%5,%6,%7}, {%8,%9}, {%0,%1,%2,%3};"
                 : "+r"(c[0]), "+r"(c[1]), "+r"(c[2]), "+r"(c[3])
                 : "r"(a[0]), "r"(a[1]), "r"(a[2]), "r"(a[3]), "r"(b0), "r"(b1));
}
__device__ __forceinline__ void mma_bf16(float* c, const uint32_t* a, uint32_t b0, uint32_t b1) {
    asm volatile("mma.sync.aligned.m16n8k16.row.col.f32.bf16.bf16.f32 "
                 "{%0,%1,%2,%3}, {%4,%5,%6,%7}, {%8,%9}, {%0,%1,%2,%3};"
                 : "+f"(c[0]), "+f"(c[1]), "+f"(c[2]), "+f"(c[3])
                 : "r"(a[0]), "r"(a[1]), "r"(a[2]), "r"(a[3]), "r"(b0), "r"(b1));
}
__device__ __forceinline__ uint32_t pack2(__nv_bfloat16 x, __nv_bfloat16 y) {
    __nv_bfloat162 t = __halves2bfloat162(x, y);
    return *(uint32_t*)&t;
}

// ---------------- weight scale: mean(|W|), two-pass deterministic ----------------
__global__ void absmean_partial(const float* __restrict__ W, int n, float* __restrict__ part) {
    __shared__ float sb[256];
    int tid = threadIdx.x;
    float s = 0.f;
    for (long i = (long)blockIdx.x * 256 + tid; i < n; i += (long)gridDim.x * 256)
        s += fabsf(W[i]);
    sb[tid] = s; __syncthreads();
    for (int o = 128; o > 0; o >>= 1) {
        if (tid < o) sb[tid] += sb[tid + o];
        __syncthreads();
    }
    if (tid == 0) part[blockIdx.x] = sb[0];
}

__global__ void wscale_final(const float* __restrict__ part, float* __restrict__ wsc) {
    __shared__ float sb[256];
    int i = blockIdx.x, tid = threadIdx.x;
    float s = part[i * 1024 + tid] + part[i * 1024 + tid + 256]
            + part[i * 1024 + tid + 512] + part[i * 1024 + tid + 768];
    sb[tid] = s; __syncthreads();
    for (int o = 128; o > 0; o >>= 1) {
        if (tid < o) sb[tid] += sb[tid + o];
        __syncthreads();
    }
    if (tid == 0) {
        float n = (i == 0 || i == 3) ? 16777216.f : 4194304.f;
        wsc[i] = fmaxf(sb[0] / n, 1e-5f);
    }
}

// ---------------- ternary weight quant: clip(round(W/ws),-1,1) packed int8x4 ----------------
__global__ void quant_w(const float* __restrict__ W, int np, const float* __restrict__ wscp,
                        int* __restrict__ out) {
    int i = blockIdx.x * blockDim.x + threadIdx.x;
    if (i >= np) return;
    float ws = *wscp;
    float4 w = ((const float4*)W)[i];
    int v0 = min(1, max(-1, __float2int_rn(__fdiv_rn(w.x, ws))));
    int v1 = min(1, max(-1, __float2int_rn(__fdiv_rn(w.y, ws))));
    int v2 = min(1, max(-1, __float2int_rn(__fdiv_rn(w.z, ws))));
    int v3 = min(1, max(-1, __float2int_rn(__fdiv_rn(w.w, ws))));
    out[i] = (v0 & 255) | ((v1 & 255) << 8) | ((v2 & 255) << 16) | ((v3 & 255) << 24);
}

// ---------------- per-token int8 activation quant (absmax) ----------------
__global__ void quant_a(const float* __restrict__ X, int* __restrict__ out,
                        float* __restrict__ inva) {
    __shared__ float sb[256];
    int row = blockIdx.x, tid = threadIdx.x;
    const float4* xr = (const float4*)(X + (size_t)row * HID);
    float4 v[4];
    float am = 0.f;
#pragma unroll
    for (int u = 0; u < 4; u++) {
        v[u] = xr[tid + u * 256];
        am = fmaxf(am, fmaxf(fmaxf(fabsf(v[u].x), fabsf(v[u].y)),
                             fmaxf(fabsf(v[u].z), fabsf(v[u].w))));
    }
    sb[tid] = am; __syncthreads();
    for (int o = 128; o > 0; o >>= 1) {
        if (tid < o) sb[tid] = fmaxf(sb[tid], sb[tid + o]);
        __syncthreads();
    }
    float amax = fmaxf(sb[0], 1e-5f);
    float sc = __fdiv_rn(127.f, amax);
    if (tid == 0) inva[row] = amax * (1.f / 127.f);
#pragma unroll
    for (int u = 0; u < 4; u++) {
        int a0 = max(-128, min(127, __float2int_rn(v[u].x * sc)));
        int a1 = max(-128, min(127, __float2int_rn(v[u].y * sc)));
        int a2 = max(-128, min(127, __float2int_rn(v[u].z * sc)));
        int a3 = max(-128, min(127, __float2int_rn(v[u].w * sc)));
        out[(size_t)row * KPACK + tid + u * 256] =
            (a0 & 255) | ((a1 & 255) << 8) | ((a2 & 255) << 16) | ((a3 & 255) << 24);
    }
}

// ============ shared int8 GEMM mainloop (128x128 CTA tile, K-chunk 64) ============
struct GemmCore {
    int acc[2][8][4];
    int wm, wn, lane;
    __device__ __forceinline__ void run(const int8_t* A, const int8_t* Bw,
                                        int m0, int n0, int tid,
                                        int8_t (*As)[128 * 80], int8_t (*Bs)[128 * 80]) {
        lane = tid & 31;
        const int wid = tid >> 5;
        wm = wid & 3; wn = wid >> 2;
        const uint32_t aB[2] = { smem_u32(As[0]), smem_u32(As[1]) };
        const uint32_t bB[2] = { smem_u32(Bs[0]), smem_u32(Bs[1]) };
        const int lr = tid >> 1, lc = (tid & 1) * 32;
        const uint32_t sOff = lr * 80 + lc;
        const int8_t* Agp = A + (size_t)(m0 + lr) * HID + lc;
        const int8_t* Bgp = Bw + (size_t)(n0 + lr) * HID + lc;

        auto load = [&](int chunk, int st) {
            const int8_t* ag = Agp + chunk * 64;
            const int8_t* bg = Bgp + chunk * 64;
            cp16(aB[st] + sOff, ag);       cp16(aB[st] + sOff + 16, ag + 16);
            cp16(bB[st] + sOff, bg);       cp16(bB[st] + sOff + 16, bg + 16);
            asm volatile("cp.async.commit_group;" ::: "memory");
        };

#pragma unroll
        for (int i = 0; i < 2; i++)
#pragma unroll
            for (int j = 0; j < 8; j++)
#pragma unroll
                for (int t = 0; t < 4; t++) acc[i][j][t] = 0;

        const uint32_t lmRow = (lane & 15) * 80 + (lane >> 4) * 16;
        const uint32_t aAddr0 = (wm * 32) * 80 + lmRow;
        const uint32_t bAddr0 = (wn * 64) * 80 + lmRow;

        const int NC = HID / 64;
        load(0, 0);
        load(1, 1);
        for (int c = 0; c < NC; c++) {
            const int st = c & 1;
            if (c < NC - 2) asm volatile("cp.async.wait_group 1;" ::: "memory");
            else            asm volatile("cp.async.wait_group 0;" ::: "memory");
            __syncthreads();
#pragma unroll
            for (int ks = 0; ks < 2; ks++) {
                uint32_t a[2][4], bf[4][4];
#pragma unroll
                for (int mt = 0; mt < 2; mt++)
                    ldm_x4(a[mt], aB[st] + aAddr0 + mt * (16 * 80) + ks * 32);
#pragma unroll
                for (int ng = 0; ng < 4; ng++)
                    ldm_x4(bf[ng], bB[st] + bAddr0 + ng * (16 * 80) + ks * 32);
#pragma unroll
                for (int mt = 0; mt < 2; mt++)
#pragma unroll
                    for (int nt = 0; nt < 8; nt++)
                        mma_s8(acc[mt][nt], a[mt], bf[nt >> 1][nt & 1], bf[nt >> 1][2 + (nt & 1)]);
            }
            __syncthreads();
            if (c + 2 < NC) load(c + 2, st);
        }
    }
};

// ---------------- fused QKV GEMM: int8 mma -> split-bf16 epilogue ----------------
__global__ void __launch_bounds__(256) gemm_qkv(const int8_t* __restrict__ A,
                                                const int8_t* __restrict__ Bw,
                                                const float* __restrict__ inva,
                                                const float* __restrict__ wsc,
                                                __nv_bfloat16* __restrict__ Qh, __nv_bfloat16* __restrict__ Ql,
                                                __nv_bfloat16* __restrict__ Kh, __nv_bfloat16* __restrict__ Kl,
                                                __nv_bfloat16* __restrict__ Vh, __nv_bfloat16* __restrict__ Vl) {
    __shared__ int8_t As[2][128 * 80];
    __shared__ int8_t Bs[2][128 * 80];
    const int m0 = blockIdx.x * 128, n0 = blockIdx.y * 128;
    GemmCore g;
    g.run(A, Bw, m0, n0, threadIdx.x, As, Bs);

    __nv_bfloat16 *H, *L; int ldc, nb; float wsv;
    if (n0 < HID)            { H = Qh; L = Ql; ldc = HID; nb = n0;             wsv = wsc[0] * QSC; }
    else if (n0 < HID + NKV) { H = Kh; L = Kl; ldc = NKV; nb = n0 - HID;       wsv = wsc[1]; }
    else                     { H = Vh; L = Vl; ldc = NKV; nb = n0 - HID - NKV; wsv = wsc[2]; }

#pragma unroll
    for (int mt = 0; mt < 2; mt++) {
        const int mlo = m0 + g.wm * 32 + mt * 16 + (g.lane >> 2);
        const float s0 = wsv * inva[mlo];
        const float s1 = wsv * inva[mlo + 8];
#pragma unroll
        for (int nt = 0; nt < 8; nt++) {
            const int n = nb + g.wn * 64 + nt * 8 + (g.lane & 3) * 2;
            float v0 = (float)g.acc[mt][nt][0] * s0, v1 = (float)g.acc[mt][nt][1] * s0;
            float v2 = (float)g.acc[mt][nt][2] * s1, v3 = (float)g.acc[mt][nt][3] * s1;
            __nv_bfloat16 h0 = __float2bfloat16(v0), h1 = __float2bfloat16(v1);
            __nv_bfloat16 h2 = __float2bfloat16(v2), h3 = __float2bfloat16(v3);
            *(__nv_bfloat162*)(H + (size_t)mlo * ldc + n) = __halves2bfloat162(h0, h1);
            *(__nv_bfloat162*)(H + (size_t)(mlo + 8) * ldc + n) = __halves2bfloat162(h2, h3);
            *(__nv_bfloat162*)(L + (size_t)mlo * ldc + n) =
                __halves2bfloat162(__float2bfloat16(v0 - __bfloat162float(h0)),
                                   __float2bfloat16(v1 - __bfloat162float(h1)));
            *(__nv_bfloat162*)(L + (size_t)(mlo + 8) * ldc + n) =
                __halves2bfloat162(__float2bfloat16(v2 - __bfloat162float(h2)),
                                   __float2bfloat16(v3 - __bfloat162float(h3)));
        }
    }
}

// ---------------- O-projection GEMM: int8 mma -> fp32 out ----------------
__global__ void __launch_bounds__(256) gemm_i8(const int8_t* __restrict__ A,
                                               const int8_t* __restrict__ Bw,
                                               const float* __restrict__ inva,
                                               const float* __restrict__ wscp,
                                               float* __restrict__ C, int N) {
    __shared__ int8_t As[2][128 * 80];
    __shared__ int8_t Bs[2][128 * 80];
    const int m0 = blockIdx.x * 128, n0 = blockIdx.y * 128;
    GemmCore g;
    g.run(A, Bw, m0, n0, threadIdx.x, As, Bs);
    const float wsv = *wscp;
#pragma unroll
    for (int mt = 0; mt < 2; mt++) {
        const int mlo = m0 + g.wm * 32 + mt * 16 + (g.lane >> 2);
        const float s0 = wsv * inva[mlo];
        const float s1 = wsv * inva[mlo + 8];
#pragma unroll
        for (int nt = 0; nt < 8; nt++) {
            const int n = n0 + g.wn * 64 + nt * 8 + (g.lane & 3) * 2;
            *(float2*)(C + (size_t)mlo * N + n) =
                make_float2((float)g.acc[mt][nt][0] * s0, (float)g.acc[mt][nt][1] * s0);
            *(float2*)(C + (size_t)(mlo + 8) * N + n) =
                make_float2((float)g.acc[mt][nt][2] * s1, (float)g.acc[mt][nt][3] * s1);
        }
    }
}

// ---------------- tensor-core flash attention v2 ----------------
// CTA = 128 q-rows (8 warps), k-tiles of 64, pre-split bf16 inputs, cp.async double buffer.
#define AP 136                          // smem pitch in bf16 (272 B)
#define TILE_B (64 * AP * 2)            // 17408 B per 64-row buffer
#define QBUF_B (128 * AP * 2)           // 34816 B per 128-row Q buffer
#define ATTN_SMEM (2 * QBUF_B + 8 * TILE_B)   // 208896 B

__global__ void __launch_bounds__(256) attn_mma(const __nv_bfloat16* __restrict__ Qh_g,
                                                const __nv_bfloat16* __restrict__ Ql_g,
                                                const __nv_bfloat16* __restrict__ Kh_g,
                                                const __nv_bfloat16* __restrict__ Kl_g,
                                                const __nv_bfloat16* __restrict__ Vh_g,
                                                const __nv_bfloat16* __restrict__ Vl_g,
                                                float* __restrict__ O) {
    extern __shared__ __nv_bfloat16 sm[];
    const int qt = 15 - blockIdx.x;          // longest first
    const int bh = blockIdx.y;
    const int b = bh >> 5, h = bh & 31, kvh = h >> 2;
    const int tid = threadIdx.x, warp = tid >> 5, lane = tid & 31;
    const int q0 = b * SEQ + qt * 128;

    const uint32_t sQh = smem_u32(sm);
    const uint32_t sQl = sQh + QBUF_B;
    const uint32_t sKV = sQl + QBUF_B;       // [st][Kh,Kl,Vh,Vl]

    // Q load (cp.async, once)
    for (int i = tid; i < 128 * 16; i += 256) {
        int r = i >> 4, c = i & 15;
        size_t gq = (size_t)(q0 + r) * HID + h * HD + c * 8;
        uint32_t so = r * (AP * 2) + c * 16;
        cp16(sQh + so, Qh_g + gq);
        cp16(sQl + so, Ql_g + gq);
    }

    auto loadKV = [&](int kt, int st) {
        const int k0r = b * SEQ + kt * 64;
        const uint32_t base = sKV + st * (4 * TILE_B);
        for (int i = tid; i < 64 * 16; i += 256) {
            int r = i >> 4, c = i & 15;
            size_t gk = (size_t)(k0r + r) * NKV + kvh * HD + c * 8;
            uint32_t so = r * (AP * 2) + c * 16;
            cp16(base + so,              Kh_g + gk);
            cp16(base + TILE_B + so,     Kl_g + gk);
            cp16(base + 2 * TILE_B + so, Vh_g + gk);
            cp16(base + 3 * TILE_B + so, Vl_g + gk);
        }
        asm volatile("cp.async.commit_group;" ::: "memory");
    };

    // ldmatrix lane address offsets (bytes)
    const uint32_t aOff  = ((warp * 16 + (lane & 15)) * AP + (lane >> 4) * 8) * 2;
    const uint32_t bkOff = ((((lane & 7) + ((lane >> 4) & 1) * 8)) * AP + ((lane >> 3) & 1) * 8) * 2;
    const uint32_t bvOff = (((lane & 7) + ((lane >> 3) & 1) * 8)) * AP * 2 + ((lane >> 4) & 1) * 16;

    float o[16][4];
#pragma unroll
    for (int nb = 0; nb < 16; nb++)
#pragma unroll
        for (int t = 0; t < 4; t++) o[nb][t] = 0.f;
    float mi0 = -1e30f, mi1 = -1e30f, l0 = 0.f, l1 = 0.f;

    const int ntile = 2 * qt + 2;
    loadKV(0, 0);     // group 0 = Q + tile 0

    for (int kt = 0; kt < ntile; kt++) {
        const int st = kt & 1;
        if (kt + 1 < ntile) loadKV(kt + 1, st ^ 1);
        if (kt + 1 < ntile) asm volatile("cp.async.wait_group 1;" ::: "memory");
        else                asm volatile("cp.async.wait_group 0;" ::: "memory");
        __syncthreads();

        const uint32_t kb = sKV + st * (4 * TILE_B);
        const uint32_t sKh_ = kb, sKl_ = kb + TILE_B, sVh_ = kb + 2 * TILE_B, sVl_ = kb + 3 * TILE_B;

        // S = Q K^T (3-term bf16 split)
        float s[8][4];
#pragma unroll
        for (int j = 0; j < 8; j++)
#pragma unroll
            for (int t = 0; t < 4; t++) s[j][t] = 0.f;

#pragma unroll
        for (int kk = 0; kk < 8; kk++) {
            uint32_t ah[4], al[4];
            ldm_x4(ah, sQh + aOff + kk * 32);
            ldm_x4(al, sQl + aOff + kk * 32);
#pragma unroll
            for (int p = 0; p < 4; p++) {
                uint32_t bh_[4], bl_[4];
                ldm_x4(bh_, sKh_ + bkOff + p * (16 * AP * 2) + kk * 32);
                ldm_x4(bl_, sKl_ + bkOff + p * (16 * AP * 2) + kk * 32);
                mma_bf16(s[2 * p],     ah, bh_[0], bh_[1]);
                mma_bf16(s[2 * p],     ah, bl_[0], bl_[1]);
                mma_bf16(s[2 * p],     al, bh_[0], bh_[1]);
                mma_bf16(s[2 * p + 1], ah, bh_[2], bh_[3]);
                mma_bf16(s[2 * p + 1], ah, bl_[2], bl_[3]);
                mma_bf16(s[2 * p + 1], al, bh_[2], bh_[3]);
            }
        }

        if (kt >= 2 * qt) {   // diagonal region: per-element causal mask
            const int rr = warp * 16 + (lane >> 2);
            const int coff = 64 * kt - 128 * qt;
#pragma unroll
            for (int j = 0; j < 8; j++) {
                int c0 = coff + j * 8 + (lane & 3) * 2;
                if (c0 > rr)          s[j][0] = -1e30f;
                if (c0 + 1 > rr)      s[j][1] = -1e30f;
                if (c0 > rr + 8)      s[j][2] = -1e30f;
                if (c0 + 1 > rr + 8)  s[j][3] = -1e30f;
            }
        }

        // base-2 online softmax
        float mt0 = -1e30f, mt1 = -1e30f;
#pragma unroll
        for (int j = 0; j < 8; j++) {
            mt0 = fmaxf(mt0, fmaxf(s[j][0], s[j][1]));
            mt1 = fmaxf(mt1, fmaxf(s[j][2], s[j][3]));
        }
        mt0 = fmaxf(mt0, __shfl_xor_sync(0xffffffffu, mt0, 1));
        mt0 = fmaxf(mt0, __shfl_xor_sync(0xffffffffu, mt0, 2));
        mt1 = fmaxf(mt1, __shfl_xor_sync(0xffffffffu, mt1, 1));
        mt1 = fmaxf(mt1, __shfl_xor_sync(0xffffffffu, mt1, 2));
        float mn0 = fmaxf(mi0, mt0), mn1 = fmaxf(mi1, mt1);
        float al0 = exp2f(mi0 - mn0), al1 = exp2f(mi1 - mn1);
        mi0 = mn0; mi1 = mn1;
        float rs0 = 0.f, rs1 = 0.f;
#pragma unroll
        for (int j = 0; j < 8; j++) {
            s[j][0] = exp2f(s[j][0] - mn0); rs0 += s[j][0];
            s[j][1] = exp2f(s[j][1] - mn0); rs0 += s[j][1];
            s[j][2] = exp2f(s[j][2] - mn1); rs1 += s[j][2];
            s[j][3] = exp2f(s[j][3] - mn1); rs1 += s[j][3];
        }
        rs0 += __shfl_xor_sync(0xffffffffu, rs0, 1);
        rs0 += __shfl_xor_sync(0xffffffffu, rs0, 2);
        rs1 += __shfl_xor_sync(0xffffffffu, rs1, 1);
        rs1 += __shfl_xor_sync(0xffffffffu, rs1, 2);
        l0 = l0 * al0 + rs0;
        l1 = l1 * al1 + rs1;
#pragma unroll
        for (int nb = 0; nb < 16; nb++) {
            o[nb][0] *= al0; o[nb][1] *= al0;
            o[nb][2] *= al1; o[nb][3] *= al1;
        }

        // O += P V (P split hi/lo in registers)
#pragma unroll
        for (int kk = 0; kk < 4; kk++) {
            uint32_t ah[4], al_[4];
#pragma unroll
            for (int half = 0; half < 2; half++) {
                const float* sp = s[2 * kk + half];
                __nv_bfloat16 h0 = __float2bfloat16(sp[0]), h1 = __float2bfloat16(sp[1]);
                __nv_bfloat16 h2 = __float2bfloat16(sp[2]), h3 = __float2bfloat16(sp[3]);
                ah[2 * half]     = pack2(h0, h1);
                ah[2 * half + 1] = pack2(h2, h3);
                al_[2 * half]     = pack2(__float2bfloat16(sp[0] - __bfloat162float(h0)),
                                          __float2bfloat16(sp[1] - __bfloat162float(h1)));
                al_[2 * half + 1] = pack2(__float2bfloat16(sp[2] - __bfloat162float(h2)),
                                          __float2bfloat16(sp[3] - __bfloat162float(h3)));
            }
#pragma unroll
            for (int j = 0; j < 8; j++) {
                uint32_t bh_[4], bl_[4];
                ldm_x4t(bh_, sVh_ + bvOff + kk * (16 * AP * 2) + j * 32);
                ldm_x4t(bl_, sVl_ + bvOff + kk * (16 * AP * 2) + j * 32);
                mma_bf16(o[2 * j],     ah,  bh_[0], bh_[1]);
                mma_bf16(o[2 * j],     ah,  bl_[0], bl_[1]);
                mma_bf16(o[2 * j],     al_, bh_[0], bh_[1]);
                mma_bf16(o[2 * j + 1], ah,  bh_[2], bh_[3]);
                mma_bf16(o[2 * j + 1], ah,  bl_[2], bl_[3]);
                mma_bf16(o[2 * j + 1], al_, bh_[2], bh_[3]);
            }
        }
        __syncthreads();
    }

    // epilogue
    const float inv0 = __fdiv_rn(1.f, l0), inv1 = __fdiv_rn(1.f, l1);
    const int r0 = q0 + warp * 16 + (lane >> 2);
    const int cbase = h * HD + (lane & 3) * 2;
#pragma unroll
    for (int nb = 0; nb < 16; nb++) {
        *(float2*)(O + (size_t)r0 * HID + cbase + nb * 8) =
            make_float2(o[nb][0] * inv0, o[nb][1] * inv0);
        *(float2*)(O + (size_t)(r0 + 8) * HID + cbase + nb * 8) =
            make_float2(o[nb][2] * inv1, o[nb][3] * inv1);
    }
}

// ---------------- launch ----------------
extern "C" void kernel_launch(void* const* d_in, const int* in_sizes, int n_in,
                              void* d_out, int out_size) {
    const float* hs = (const float*)d_in[0];
    // d_in[1] = attention_mask: exactly the causal -1e9 mask; handled analytically.
    const float* Wq = (const float*)d_in[2];
    const float* Wk = (const float*)d_in[3];
    const float* Wv = (const float*)d_in[4];
    const float* Wo = (const float*)d_in[5];

    void* p;
    cudaGetSymbolAddress(&p, g_xq);   int*   xq   = (int*)p;
    cudaGetSymbolAddress(&p, g_inva); float* inva = (float*)p;
    cudaGetSymbolAddress(&p, g_wqkv); int*   wqkv = (int*)p;
    cudaGetSymbolAddress(&p, g_woq);  int*   woq  = (int*)p;
    cudaGetSymbolAddress(&p, g_qh);   __nv_bfloat16* qh = (__nv_bfloat16*)p;
    cudaGetSymbolAddress(&p, g_ql);   __nv_bfloat16* ql = (__nv_bfloat16*)p;
    cudaGetSymbolAddress(&p, g_kh);   __nv_bfloat16* kh = (__nv_bfloat16*)p;
    cudaGetSymbolAddress(&p, g_kl);   __nv_bfloat16* kl = (__nv_bfloat16*)p;
    cudaGetSymbolAddress(&p, g_vh);   __nv_bfloat16* vh = (__nv_bfloat16*)p;
    cudaGetSymbolAddress(&p, g_vl);   __nv_bfloat16* vl = (__nv_bfloat16*)p;
    cudaGetSymbolAddress(&p, g_ao);   float* ao   = (float*)p;
    cudaGetSymbolAddress(&p, g_part); float* part = (float*)p;
    cudaGetSymbolAddress(&p, g_wsc);  float* wsc  = (float*)p;

    cudaFuncSetAttribute(attn_mma, cudaFuncAttributeMaxDynamicSharedMemorySize, ATTN_SMEM);

    // weight scales (mean |W|)
    absmean_partial<<<1024, 256>>>(Wq, HID * HID, part + 0);
    absmean_partial<<<1024, 256>>>(Wk, NKV * HID, part + 1024);
    absmean_partial<<<1024, 256>>>(Wv, NKV * HID, part + 2048);
    absmean_partial<<<1024, 256>>>(Wo, HID * HID, part + 3072);
    wscale_final<<<4, 256>>>(part, wsc);

    // ternary weight quantization into fused Q|K|V buffer + O buffer
    quant_w<<<(HID * KPACK + 255) / 256, 256>>>(Wq, HID * KPACK, wsc + 0, wqkv);
    quant_w<<<(NKV * KPACK + 255) / 256, 256>>>(Wk, NKV * KPACK, wsc + 1, wqkv + HID * KPACK);
    quant_w<<<(NKV * KPACK + 255) / 256, 256>>>(Wv, NKV * KPACK, wsc + 2, wqkv + (HID + NKV) * KPACK);
    quant_w<<<(HID * KPACK + 255) / 256, 256>>>(Wo, HID * KPACK, wsc + 3, woq);

    // activation quant + fused QKV projection with split-bf16 epilogue
    quant_a<<<MTOK, 256>>>(hs, xq, inva);
    gemm_qkv<<<dim3(32, 48), 256>>>((const int8_t*)xq, (const int8_t*)wqkv, inva, wsc,
                                    qh, ql, kh, kl, vh, vl);

    // tensor-core flash attention (128-row CTAs, double-buffered)
    attn_mma<<<dim3(16, 64), 256, ATTN_SMEM>>>(qh, ql, kh, kl, vh, vl, ao);

    // output projection
    quant_a<<<MTOK, 256>>>(ao, xq, inva);
    gemm_i8<<<dim3(32, 32), 256>>>((const int8_t*)xq, (const int8_t*)woq, inva, wsc + 3,
                                   (float*)d_out, HID);
}

// round 6
// speedup vs baseline: 2.9358x; 1.0134x over previous
#include <cuda_runtime.h>
#include <cuda_bf16.h>
#include <cstdint>

#define SEQ   2048
#define MTOK  4096
#define HID   4096
#define KPACK 1024
#define NKV   1024
#define HD    128
#define NQKV  6144
#define QSC   0.08838834764831845f   // 1/sqrt(128)

// ---------------- scratch (device globals) ----------------
__device__ int   g_xq[MTOK * KPACK];
__device__ float g_inva[MTOK];
__device__ int   g_wqkv[NQKV * KPACK];
__device__ int   g_woq[HID * KPACK];
__device__ __nv_bfloat16 g_qh[(size_t)MTOK * HID];
__device__ __nv_bfloat16 g_ql[(size_t)MTOK * HID];
__device__ __nv_bfloat16 g_kh[(size_t)MTOK * NKV];
__device__ __nv_bfloat16 g_kl[(size_t)MTOK * NKV];
__device__ __nv_bfloat16 g_vh[(size_t)MTOK * NKV];
__device__ __nv_bfloat16 g_vl[(size_t)MTOK * NKV];
__device__ float g_ao[(size_t)MTOK * HID];
__device__ float g_part[4 * 1024];
__device__ float g_wsc[4];

__device__ __forceinline__ uint32_t smem_u32(const void* p) {
    uint32_t a;
    asm("{ .reg .u64 t; cvta.to.shared.u64 t, %1; cvt.u32.u64 %0, t; }" : "=r"(a) : "l"(p));
    return a;
}
__device__ __forceinline__ void cp16(uint32_t dst, const void* src) {
    asm volatile("cp.async.cg.shared.global [%0], [%1], 16;" :: "r"(dst), "l"(src));
}
__device__ __forceinline__ void ldm_x4(uint32_t* r, uint32_t addr) {
    asm volatile("ldmatrix.sync.aligned.m8n8.x4.shared.b16 {%0,%1,%2,%3}, [%4];"
                 : "=r"(r[0]), "=r"(r[1]), "=r"(r[2]), "=r"(r[3]) : "r"(addr));
}
__device__ __forceinline__ void ldm_x4t(uint32_t* r, uint32_t addr) {
    asm volatile("ldmatrix.sync.aligned.m8n8.x4.trans.shared.b16 {%0,%1,%2,%3}, [%4];"
                 : "=r"(r[0]), "=r"(r[1]), "=r"(r[2]), "=r"(r[3]) : "r"(addr));
}
__device__ __forceinline__ void mma_s8(int* c, const uint32_t* a, uint32_t b0, uint32_t b1) {
    asm volatile("mma.sync.aligned.m16n8k32.row.col.s32.s8.s8.s32 "
                 "{%0,%1,%2,%3}, {%4,%5,%6,%7}, {%8,%9}, {%0,%1,%2,%3};"
                 : "+r"(c[0]), "+r"(c[1]), "+r"(c[2]), "+r"(c[3])
                 : "r"(a[0]), "r"(a[1]), "r"(a[2]), "r"(a[3]), "r"(b0), "r"(b1));
}
__device__ __forceinline__ void mma_bf16(float* c, const uint32_t* a, uint32_t b0, uint32_t b1) {
    asm volatile("mma.sync.aligned.m16n8k16.row.col.f32.bf16.bf16.f32 "
                 "{%0,%1,%2,%3}, {%4,%5,%6,%7}, {%8,%9}, {%0,%1,%2,%3};"
                 : "+f"(c[0]), "+f"(c[1]), "+f"(c[2]), "+f"(c[3])
                 : "r"(a[0]), "r"(a[1]), "r"(a[2]), "r"(a[3]), "r"(b0), "r"(b1));
}
__device__ __forceinline__ uint32_t pack2(__nv_bfloat16 x, __nv_bfloat16 y) {
    __nv_bfloat162 t = __halves2bfloat162(x, y);
    return *(uint32_t*)&t;
}

// ---------------- weight scale: mean(|W|) ----------------
__global__ void absmean_partial(const float* __restrict__ W, int n, float* __restrict__ part) {
    __shared__ float sb[256];
    int tid = threadIdx.x;
    float s = 0.f;
    for (long i = (long)blockIdx.x * 256 + tid; i < n; i += (long)gridDim.x * 256)
        s += fabsf(W[i]);
    sb[tid] = s; __syncthreads();
    for (int o = 128; o > 0; o >>= 1) {
        if (tid < o) sb[tid] += sb[tid + o];
        __syncthreads();
    }
    if (tid == 0) part[blockIdx.x] = sb[0];
}

__global__ void wscale_final(const float* __restrict__ part, float* __restrict__ wsc) {
    __shared__ float sb[256];
    int i = blockIdx.x, tid = threadIdx.x;
    float s = part[i * 1024 + tid] + part[i * 1024 + tid + 256]
            + part[i * 1024 + tid + 512] + part[i * 1024 + tid + 768];
    sb[tid] = s; __syncthreads();
    for (int o = 128; o > 0; o >>= 1) {
        if (tid < o) sb[tid] += sb[tid + o];
        __syncthreads();
    }
    if (tid == 0) {
        float n = (i == 0 || i == 3) ? 16777216.f : 4194304.f;
        wsc[i] = fmaxf(sb[0] / n, 1e-5f);
    }
}

// ---------------- ternary weight quant ----------------
__global__ void quant_w(const float* __restrict__ W, int np, const float* __restrict__ wscp,
                        int* __restrict__ out) {
    int i = blockIdx.x * blockDim.x + threadIdx.x;
    if (i >= np) return;
    float ws = *wscp;
    float4 w = ((const float4*)W)[i];
    int v0 = min(1, max(-1, __float2int_rn(__fdiv_rn(w.x, ws))));
    int v1 = min(1, max(-1, __float2int_rn(__fdiv_rn(w.y, ws))));
    int v2 = min(1, max(-1, __float2int_rn(__fdiv_rn(w.z, ws))));
    int v3 = min(1, max(-1, __float2int_rn(__fdiv_rn(w.w, ws))));
    out[i] = (v0 & 255) | ((v1 & 255) << 8) | ((v2 & 255) << 16) | ((v3 & 255) << 24);
}

// ---------------- per-token int8 activation quant ----------------
__global__ void quant_a(const float* __restrict__ X, int* __restrict__ out,
                        float* __restrict__ inva) {
    __shared__ float sb[256];
    int row = blockIdx.x, tid = threadIdx.x;
    const float4* xr = (const float4*)(X + (size_t)row * HID);
    float4 v[4];
    float am = 0.f;
#pragma unroll
    for (int u = 0; u < 4; u++) {
        v[u] = xr[tid + u * 256];
        am = fmaxf(am, fmaxf(fmaxf(fabsf(v[u].x), fabsf(v[u].y)),
                             fmaxf(fabsf(v[u].z), fabsf(v[u].w))));
    }
    sb[tid] = am; __syncthreads();
    for (int o = 128; o > 0; o >>= 1) {
        if (tid < o) sb[tid] = fmaxf(sb[tid], sb[tid + o]);
        __syncthreads();
    }
    float amax = fmaxf(sb[0], 1e-5f);
    float sc = __fdiv_rn(127.f, amax);
    if (tid == 0) inva[row] = amax * (1.f / 127.f);
#pragma unroll
    for (int u = 0; u < 4; u++) {
        int a0 = max(-128, min(127, __float2int_rn(v[u].x * sc)));
        int a1 = max(-128, min(127, __float2int_rn(v[u].y * sc)));
        int a2 = max(-128, min(127, __float2int_rn(v[u].z * sc)));
        int a3 = max(-128, min(127, __float2int_rn(v[u].w * sc)));
        out[(size_t)row * KPACK + tid + u * 256] =
            (a0 & 255) | ((a1 & 255) << 8) | ((a2 & 255) << 16) | ((a3 & 255) << 24);
    }
}

// ============ int8 GEMM mainloop: 128x128 tile, K-chunk 128, 3-stage, 1 sync/chunk ============
#define GP 144                       // smem row pitch (bytes)
#define GSTAGE (128 * GP)            // 18432 per matrix per stage
#define GEMM_SMEM (3 * 2 * GSTAGE)   // 110592

struct GemmCore {
    int acc[2][8][4];
    int wm, wn, lane;
    __device__ __forceinline__ void run(const int8_t* __restrict__ A,
                                        const int8_t* __restrict__ Bw,
                                        int m0, int n0, int tid, uint32_t sb) {
        lane = tid & 31;
        wm = (tid >> 5) & 3; wn = tid >> 7;
        uint32_t soff[4]; size_t ga[4], gb[4];
#pragma unroll
        for (int p = 0; p < 4; p++) {
            int u = tid + p * 256, r = u >> 3, c = u & 7;
            soff[p] = r * GP + c * 16;
            ga[p] = (size_t)(m0 + r) * HID + c * 16;
            gb[p] = (size_t)(n0 + r) * HID + c * 16;
        }
        auto load = [&](int ch, int st) {
            const uint32_t ab = sb + st * (2 * GSTAGE), bb = ab + GSTAGE;
#pragma unroll
            for (int p = 0; p < 4; p++) cp16(ab + soff[p], A + ga[p] + ch * 128);
#pragma unroll
            for (int p = 0; p < 4; p++) cp16(bb + soff[p], Bw + gb[p] + ch * 128);
            asm volatile("cp.async.commit_group;" ::: "memory");
        };
#pragma unroll
        for (int i = 0; i < 2; i++)
#pragma unroll
            for (int j = 0; j < 8; j++)
#pragma unroll
                for (int t = 0; t < 4; t++) acc[i][j][t] = 0;

        const uint32_t lmRow = (lane & 15) * GP + (lane >> 4) * 16;
        const uint32_t aA0 = wm * 32 * GP + lmRow;
        const uint32_t bA0 = wn * 64 * GP + lmRow;

        const int NC = HID / 128;    // 32
        load(0, 0); load(1, 1);
        int st = 0;
        for (int c = 0; c < NC; c++) {
            if (c < NC - 1) asm volatile("cp.async.wait_group 1;" ::: "memory");
            else            asm volatile("cp.async.wait_group 0;" ::: "memory");
            __syncthreads();
            if (c + 2 < NC) { int s2 = st + 2; if (s2 >= 3) s2 -= 3; load(c + 2, s2); }
            const uint32_t ab = sb + st * (2 * GSTAGE), bb = ab + GSTAGE;
#pragma unroll
            for (int ks = 0; ks < 4; ks++) {
                uint32_t a[2][4], bf[4][4];
#pragma unroll
                for (int mt = 0; mt < 2; mt++)
                    ldm_x4(a[mt], ab + aA0 + mt * (16 * GP) + ks * 32);
#pragma unroll
                for (int ng = 0; ng < 4; ng++)
                    ldm_x4(bf[ng], bb + bA0 + ng * (16 * GP) + ks * 32);
#pragma unroll
                for (int mt = 0; mt < 2; mt++)
#pragma unroll
                    for (int nt = 0; nt < 8; nt++)
                        mma_s8(acc[mt][nt], a[mt], bf[nt >> 1][nt & 1], bf[nt >> 1][2 + (nt & 1)]);
            }
            st++; if (st == 3) st = 0;
        }
    }
};

// ---------------- fused QKV GEMM: int8 mma -> split-bf16 epilogue ----------------
__global__ void __launch_bounds__(256) gemm_qkv(const int8_t* __restrict__ A,
                                                const int8_t* __restrict__ Bw,
                                                const float* __restrict__ inva,
                                                const float* __restrict__ wsc,
                                                __nv_bfloat16* __restrict__ Qh, __nv_bfloat16* __restrict__ Ql,
                                                __nv_bfloat16* __restrict__ Kh, __nv_bfloat16* __restrict__ Kl,
                                                __nv_bfloat16* __restrict__ Vh, __nv_bfloat16* __restrict__ Vl) {
    extern __shared__ char gsm[];
    const int m0 = blockIdx.x * 128, n0 = blockIdx.y * 128;
    GemmCore g;
    g.run(A, Bw, m0, n0, threadIdx.x, smem_u32(gsm));

    __nv_bfloat16 *H, *L; int ldc, nb; float wsv;
    if (n0 < HID)            { H = Qh; L = Ql; ldc = HID; nb = n0;             wsv = wsc[0] * QSC; }
    else if (n0 < HID + NKV) { H = Kh; L = Kl; ldc = NKV; nb = n0 - HID;       wsv = wsc[1]; }
    else                     { H = Vh; L = Vl; ldc = NKV; nb = n0 - HID - NKV; wsv = wsc[2]; }

#pragma unroll
    for (int mt = 0; mt < 2; mt++) {
        const int mlo = m0 + g.wm * 32 + mt * 16 + (g.lane >> 2);
        const float s0 = wsv * inva[mlo];
        const float s1 = wsv * inva[mlo + 8];
#pragma unroll
        for (int nt = 0; nt < 8; nt++) {
            const int n = nb + g.wn * 64 + nt * 8 + (g.lane & 3) * 2;
            float v0 = (float)g.acc[mt][nt][0] * s0, v1 = (float)g.acc[mt][nt][1] * s0;
            float v2 = (float)g.acc[mt][nt][2] * s1, v3 = (float)g.acc[mt][nt][3] * s1;
            __nv_bfloat16 h0 = __float2bfloat16(v0), h1 = __float2bfloat16(v1);
            __nv_bfloat16 h2 = __float2bfloat16(v2), h3 = __float2bfloat16(v3);
            *(__nv_bfloat162*)(H + (size_t)mlo * ldc + n) = __halves2bfloat162(h0, h1);
            *(__nv_bfloat162*)(H + (size_t)(mlo + 8) * ldc + n) = __halves2bfloat162(h2, h3);
            *(__nv_bfloat162*)(L + (size_t)mlo * ldc + n) =
                __halves2bfloat162(__float2bfloat16(v0 - __bfloat162float(h0)),
                                   __float2bfloat16(v1 - __bfloat162float(h1)));
            *(__nv_bfloat162*)(L + (size_t)(mlo + 8) * ldc + n) =
                __halves2bfloat162(__float2bfloat16(v2 - __bfloat162float(h2)),
                                   __float2bfloat16(v3 - __bfloat162float(h3)));
        }
    }
}

// ---------------- O-projection GEMM ----------------
__global__ void __launch_bounds__(256) gemm_i8(const int8_t* __restrict__ A,
                                               const int8_t* __restrict__ Bw,
                                               const float* __restrict__ inva,
                                               const float* __restrict__ wscp,
                                               float* __restrict__ C, int N) {
    extern __shared__ char gsm[];
    const int m0 = blockIdx.x * 128, n0 = blockIdx.y * 128;
    GemmCore g;
    g.run(A, Bw, m0, n0, threadIdx.x, smem_u32(gsm));
    const float wsv = *wscp;
#pragma unroll
    for (int mt = 0; mt < 2; mt++) {
        const int mlo = m0 + g.wm * 32 + mt * 16 + (g.lane >> 2);
        const float s0 = wsv * inva[mlo];
        const float s1 = wsv * inva[mlo + 8];
#pragma unroll
        for (int nt = 0; nt < 8; nt++) {
            const int n = n0 + g.wn * 64 + nt * 8 + (g.lane & 3) * 2;
            *(float2*)(C + (size_t)mlo * N + n) =
                make_float2((float)g.acc[mt][nt][0] * s0, (float)g.acc[mt][nt][1] * s0);
            *(float2*)(C + (size_t)(mlo + 8) * N + n) =
                make_float2((float)g.acc[mt][nt][2] * s1, (float)g.acc[mt][nt][3] * s1);
        }
    }
}

// ---------------- tensor-core flash attention v3 ----------------
// CTA = 128 q-rows (8 warps). Q frags in registers (direct gmem load).
// KV: 3-stage cp.async ring, one __syncthreads per 64-col tile. Deferred l-reduction.
#define KVP 272                         // KV smem row pitch (bytes)
#define TILE_B (64 * KVP)               // 17408
#define STAGE_B (4 * TILE_B)            // Kh,Kl,Vh,Vl = 69632
#define ATTN_SMEM (3 * STAGE_B)         // 208896

__global__ void __launch_bounds__(256, 1) attn_mma(const __nv_bfloat16* __restrict__ Qh_g,
                                                   const __nv_bfloat16* __restrict__ Ql_g,
                                                   const __nv_bfloat16* __restrict__ Kh_g,
                                                   const __nv_bfloat16* __restrict__ Kl_g,
                                                   const __nv_bfloat16* __restrict__ Vh_g,
                                                   const __nv_bfloat16* __restrict__ Vl_g,
                                                   float* __restrict__ O) {
    extern __shared__ char smraw[];
    const uint32_t sKV = smem_u32(smraw);

    const int qt = 15 - blockIdx.x;          // longest first
    const int bh = blockIdx.y;
    const int b = bh >> 5, h = bh & 31, kvh = h >> 2;
    const int tid = threadIdx.x, warp = tid >> 5, lane = tid & 31;
    const int q0 = b * SEQ + qt * 128;
    const int ntile = 2 * qt + 2;

    auto loadKV = [&](int kt, int st) {
        const int k0r = b * SEQ + kt * 64;
        const uint32_t base = sKV + st * STAGE_B;
#pragma unroll
        for (int p = 0; p < 4; p++) {
            int i = tid + p * 256;           // 1024 16B units
            int r = i >> 4, c = i & 15;
            size_t gk = (size_t)(k0r + r) * NKV + kvh * HD + c * 8;
            uint32_t so = r * KVP + c * 16;
            cp16(base + so,              Kh_g + gk);
            cp16(base + TILE_B + so,     Kl_g + gk);
            cp16(base + 2 * TILE_B + so, Vh_g + gk);
            cp16(base + 3 * TILE_B + so, Vl_g + gk);
        }
        asm volatile("cp.async.commit_group;" ::: "memory");
    };

    loadKV(0, 0);
    if (ntile > 1) loadKV(1, 1);

    // Q fragments direct from gmem (PTX m16n8k16 A-frag layout)
    uint32_t qfh[8][4], qfl[8][4];
    {
        const size_t qoff = (size_t)(q0 + warp * 16 + (lane >> 2)) * HID + h * HD + (lane & 3) * 2;
        const __nv_bfloat16* qp = Qh_g + qoff;
        const __nv_bfloat16* qpl = Ql_g + qoff;
#pragma unroll
        for (int kk = 0; kk < 8; kk++) {
            qfh[kk][0] = *(const uint32_t*)(qp + kk * 16);
            qfh[kk][1] = *(const uint32_t*)(qp + 8 * HID + kk * 16);
            qfh[kk][2] = *(const uint32_t*)(qp + kk * 16 + 8);
            qfh[kk][3] = *(const uint32_t*)(qp + 8 * HID + kk * 16 + 8);
            qfl[kk][0] = *(const uint32_t*)(qpl + kk * 16);
            qfl[kk][1] = *(const uint32_t*)(qpl + 8 * HID + kk * 16);
            qfl[kk][2] = *(const uint32_t*)(qpl + kk * 16 + 8);
            qfl[kk][3] = *(const uint32_t*)(qpl + 8 * HID + kk * 16 + 8);
        }
    }

    // ldmatrix lane address offsets (bytes), pitch KVP
    const uint32_t bkOff = ((lane & 7) + ((lane >> 4) & 1) * 8) * KVP + ((lane >> 3) & 1) * 16;
    const uint32_t bvOff = ((lane & 7) + ((lane >> 3) & 1) * 8) * KVP + ((lane >> 4) & 1) * 16;

    float o[16][4];
#pragma unroll
    for (int nb = 0; nb < 16; nb++)
#pragma unroll
        for (int t = 0; t < 4; t++) o[nb][t] = 0.f;
    float mi0 = -1e30f, mi1 = -1e30f, l0 = 0.f, l1 = 0.f;

    int st = 0;
    for (int kt = 0; kt < ntile; kt++) {
        if (kt < ntile - 1) asm volatile("cp.async.wait_group 1;" ::: "memory");
        else                asm volatile("cp.async.wait_group 0;" ::: "memory");
        __syncthreads();
        if (kt + 2 < ntile) { int s2 = st + 2; if (s2 >= 3) s2 -= 3; loadKV(kt + 2, s2); }

        const uint32_t kb = sKV + st * STAGE_B;
        const uint32_t sKh_ = kb, sKl_ = kb + TILE_B, sVh_ = kb + 2 * TILE_B, sVl_ = kb + 3 * TILE_B;

        // S = Q K^T (3-term bf16 split)
        float s[8][4];
#pragma unroll
        for (int j = 0; j < 8; j++)
#pragma unroll
            for (int t = 0; t < 4; t++) s[j][t] = 0.f;

#pragma unroll
        for (int kk = 0; kk < 8; kk++) {
#pragma unroll
            for (int p = 0; p < 4; p++) {
                uint32_t bh_[4], bl_[4];
                ldm_x4(bh_, sKh_ + bkOff + p * (16 * KVP) + kk * 32);
                ldm_x4(bl_, sKl_ + bkOff + p * (16 * KVP) + kk * 32);
                mma_bf16(s[2 * p],     qfh[kk], bh_[0], bh_[1]);
                mma_bf16(s[2 * p],     qfh[kk], bl_[0], bl_[1]);
                mma_bf16(s[2 * p],     qfl[kk], bh_[0], bh_[1]);
                mma_bf16(s[2 * p + 1], qfh[kk], bh_[2], bh_[3]);
                mma_bf16(s[2 * p + 1], qfh[kk], bl_[2], bl_[3]);
                mma_bf16(s[2 * p + 1], qfl[kk], bh_[2], bh_[3]);
            }
        }

        if (kt >= 2 * qt) {   // diagonal region causal mask
            const int rr = warp * 16 + (lane >> 2);
            const int coff = 64 * kt - 128 * qt;
#pragma unroll
            for (int j = 0; j < 8; j++) {
                int c0 = coff + j * 8 + (lane & 3) * 2;
                if (c0 > rr)          s[j][0] = -1e30f;
                if (c0 + 1 > rr)      s[j][1] = -1e30f;
                if (c0 > rr + 8)      s[j][2] = -1e30f;
                if (c0 + 1 > rr + 8)  s[j][3] = -1e30f;
            }
        }

        // base-2 online softmax (max reduced per tile; sum deferred per-thread)
        float mt0 = -1e30f, mt1 = -1e30f;
#pragma unroll
        for (int j = 0; j < 8; j++) {
            mt0 = fmaxf(mt0, fmaxf(s[j][0], s[j][1]));
            mt1 = fmaxf(mt1, fmaxf(s[j][2], s[j][3]));
        }
        mt0 = fmaxf(mt0, __shfl_xor_sync(0xffffffffu, mt0, 1));
        mt0 = fmaxf(mt0, __shfl_xor_sync(0xffffffffu, mt0, 2));
        mt1 = fmaxf(mt1, __shfl_xor_sync(0xffffffffu, mt1, 1));
        mt1 = fmaxf(mt1, __shfl_xor_sync(0xffffffffu, mt1, 2));
        float mn0 = fmaxf(mi0, mt0), mn1 = fmaxf(mi1, mt1);
        float al0 = exp2f(mi0 - mn0), al1 = exp2f(mi1 - mn1);
        mi0 = mn0; mi1 = mn1;
        float rs0 = 0.f, rs1 = 0.f;
#pragma unroll
        for (int j = 0; j < 8; j++) {
            s[j][0] = exp2f(s[j][0] - mn0); rs0 += s[j][0];
            s[j][1] = exp2f(s[j][1] - mn0); rs0 += s[j][1];
            s[j][2] = exp2f(s[j][2] - mn1); rs1 += s[j][2];
            s[j][3] = exp2f(s[j][3] - mn1); rs1 += s[j][3];
        }
        l0 = l0 * al0 + rs0;         // per-thread partial; reduced after loop
        l1 = l1 * al1 + rs1;
#pragma unroll
        for (int nb = 0; nb < 16; nb++) {
            o[nb][0] *= al0; o[nb][1] *= al0;
            o[nb][2] *= al1; o[nb][3] *= al1;
        }

        // O += P V (P split hi/lo in registers)
#pragma unroll
        for (int kk = 0; kk < 4; kk++) {
            uint32_t ah[4], al_[4];
#pragma unroll
            for (int half = 0; half < 2; half++) {
                const float* sp = s[2 * kk + half];
                __nv_bfloat16 h0 = __float2bfloat16(sp[0]), h1 = __float2bfloat16(sp[1]);
                __nv_bfloat16 h2 = __float2bfloat16(sp[2]), h3 = __float2bfloat16(sp[3]);
                ah[2 * half]     = pack2(h0, h1);
                ah[2 * half + 1] = pack2(h2, h3);
                al_[2 * half]     = pack2(__float2bfloat16(sp[0] - __bfloat162float(h0)),
                                          __float2bfloat16(sp[1] - __bfloat162float(h1)));
                al_[2 * half + 1] = pack2(__float2bfloat16(sp[2] - __bfloat162float(h2)),
                                          __float2bfloat16(sp[3] - __bfloat162float(h3)));
            }
#pragma unroll
            for (int j = 0; j < 8; j++) {
                uint32_t bh_[4], bl_[4];
                ldm_x4t(bh_, sVh_ + bvOff + kk * (16 * KVP) + j * 32);
                ldm_x4t(bl_, sVl_ + bvOff + kk * (16 * KVP) + j * 32);
                mma_bf16(o[2 * j],     ah,  bh_[0], bh_[1]);
                mma_bf16(o[2 * j],     ah,  bl_[0], bl_[1]);
                mma_bf16(o[2 * j],     al_, bh_[0], bh_[1]);
                mma_bf16(o[2 * j + 1], ah,  bh_[2], bh_[3]);
                mma_bf16(o[2 * j + 1], ah,  bl_[2], bl_[3]);
                mma_bf16(o[2 * j + 1], al_, bh_[2], bh_[3]);
            }
        }
        st++; if (st == 3) st = 0;
    }

    // final l reduction + epilogue
    l0 += __shfl_xor_sync(0xffffffffu, l0, 1);
    l0 += __shfl_xor_sync(0xffffffffu, l0, 2);
    l1 += __shfl_xor_sync(0xffffffffu, l1, 1);
    l1 += __shfl_xor_sync(0xffffffffu, l1, 2);
    const float inv0 = __fdiv_rn(1.f, l0), inv1 = __fdiv_rn(1.f, l1);
    const int r0 = q0 + warp * 16 + (lane >> 2);
    const int cbase = h * HD + (lane & 3) * 2;
#pragma unroll
    for (int nb = 0; nb < 16; nb++) {
        *(float2*)(O + (size_t)r0 * HID + cbase + nb * 8) =
            make_float2(o[nb][0] * inv0, o[nb][1] * inv0);
        *(float2*)(O + (size_t)(r0 + 8) * HID + cbase + nb * 8) =
            make_float2(o[nb][2] * inv1, o[nb][3] * inv1);
    }
}

// ---------------- launch ----------------
extern "C" void kernel_launch(void* const* d_in, const int* in_sizes, int n_in,
                              void* d_out, int out_size) {
    const float* hs = (const float*)d_in[0];
    // d_in[1] = attention_mask: exactly the causal -1e9 mask; handled analytically.
    const float* Wq = (const float*)d_in[2];
    const float* Wk = (const float*)d_in[3];
    const float* Wv = (const float*)d_in[4];
    const float* Wo = (const float*)d_in[5];

    void* p;
    cudaGetSymbolAddress(&p, g_xq);   int*   xq   = (int*)p;
    cudaGetSymbolAddress(&p, g_inva); float* inva = (float*)p;
    cudaGetSymbolAddress(&p, g_wqkv); int*   wqkv = (int*)p;
    cudaGetSymbolAddress(&p, g_woq);  int*   woq  = (int*)p;
    cudaGetSymbolAddress(&p, g_qh);   __nv_bfloat16* qh = (__nv_bfloat16*)p;
    cudaGetSymbolAddress(&p, g_ql);   __nv_bfloat16* ql = (__nv_bfloat16*)p;
    cudaGetSymbolAddress(&p, g_kh);   __nv_bfloat16* kh = (__nv_bfloat16*)p;
    cudaGetSymbolAddress(&p, g_kl);   __nv_bfloat16* kl = (__nv_bfloat16*)p;
    cudaGetSymbolAddress(&p, g_vh);   __nv_bfloat16* vh = (__nv_bfloat16*)p;
    cudaGetSymbolAddress(&p, g_vl);   __nv_bfloat16* vl = (__nv_bfloat16*)p;
    cudaGetSymbolAddress(&p, g_ao);   float* ao   = (float*)p;
    cudaGetSymbolAddress(&p, g_part); float* part = (float*)p;
    cudaGetSymbolAddress(&p, g_wsc);  float* wsc  = (float*)p;

    cudaFuncSetAttribute(attn_mma, cudaFuncAttributeMaxDynamicSharedMemorySize, ATTN_SMEM);
    cudaFuncSetAttribute(gemm_qkv, cudaFuncAttributeMaxDynamicSharedMemorySize, GEMM_SMEM);
    cudaFuncSetAttribute(gemm_i8,  cudaFuncAttributeMaxDynamicSharedMemorySize, GEMM_SMEM);

    // weight scales (mean |W|)
    absmean_partial<<<1024, 256>>>(Wq, HID * HID, part + 0);
    absmean_partial<<<1024, 256>>>(Wk, NKV * HID, part + 1024);
    absmean_partial<<<1024, 256>>>(Wv, NKV * HID, part + 2048);
    absmean_partial<<<1024, 256>>>(Wo, HID * HID, part + 3072);
    wscale_final<<<4, 256>>>(part, wsc);

    // ternary weight quantization into fused Q|K|V buffer + O buffer
    quant_w<<<(HID * KPACK + 255) / 256, 256>>>(Wq, HID * KPACK, wsc + 0, wqkv);
    quant_w<<<(NKV * KPACK + 255) / 256, 256>>>(Wk, NKV * KPACK, wsc + 1, wqkv + HID * KPACK);
    quant_w<<<(NKV * KPACK + 255) / 256, 256>>>(Wv, NKV * KPACK, wsc + 2, wqkv + (HID + NKV) * KPACK);
    quant_w<<<(HID * KPACK + 255) / 256, 256>>>(Wo, HID * KPACK, wsc + 3, woq);

    // activation quant + fused QKV projection with split-bf16 epilogue
    quant_a<<<MTOK, 256>>>(hs, xq, inva);
    gemm_qkv<<<dim3(32, 48), 256, GEMM_SMEM>>>((const int8_t*)xq, (const int8_t*)wqkv, inva, wsc,
                                               qh, ql, kh, kl, vh, vl);

    // tensor-core flash attention
    attn_mma<<<dim3(16, 64), 256, ATTN_SMEM>>>(qh, ql, kh, kl, vh, vl, ao);

    // output projection
    quant_a<<<MTOK, 256>>>(ao, xq, inva);
    gemm_i8<<<dim3(32, 32), 256, GEMM_SMEM>>>((const int8_t*)xq, (const int8_t*)woq, inva, wsc + 3,
                                              (float*)d_out, HID);
}